// round 11
// baseline (speedup 1.0000x reference)
#include <cuda_runtime.h>
#include <cuda_fp16.h>
#include <cstdint>

#define NROWS 32768
#define D 256
#define K 4096
#define DECAY 0.99f
#define ONE_MINUS_DECAY 0.01f
#define EPSV 1e-5f
#define COMMIT 0.25f

static const size_t OFF_Q    = 0;
static const size_t OFF_LOSS = 8388608;
static const size_t OFF_PERP = 8388609;
static const size_t OFF_IDX  = 8388610;
static const size_t OFF_NE   = 8421378;

// -------- device scratch --------
__device__ float g_ce[K];
__device__ float g_ET[(size_t)K * D];
__device__ __align__(16) __half g_xh[(size_t)NROWS * D];
__device__ __align__(16) __half g_eh[(size_t)K * D];
__device__ float g_dw[(size_t)D * K];             // [d][k]
__device__ int   g_counts[K];
__device__ float4 g_t2[(size_t)NROWS * 32];       // [row][cg] = {v1, i1, v2, i2}
__device__ float g_loss;
__device__ float g_bias;
__device__ float g_cnorm[K];

// ================= PTX helpers =================
__device__ __forceinline__ uint32_t smem_to_u32(const void* p) {
    uint32_t a;
    asm("{ .reg .u64 t; cvta.to.shared.u64 t, %1; cvt.u32.u64 %0, t; }" : "=r"(a) : "l"(p));
    return a;
}
__device__ __forceinline__ void cp16(uint32_t saddr, const void* g) {
    asm volatile("cp.async.cg.shared.global [%0], [%1], 16;" :: "r"(saddr), "l"(g));
}
#define CP_COMMIT() asm volatile("cp.async.commit_group;" ::: "memory")
#define CP_WAIT2()  asm volatile("cp.async.wait_group 2;" ::: "memory")

#define LDSM4(r0, r1, r2, r3, a) \
    asm volatile("ldmatrix.sync.aligned.m8n8.x4.shared.b16 {%0,%1,%2,%3}, [%4];" \
        : "=r"(r0), "=r"(r1), "=r"(r2), "=r"(r3) : "r"(a))

__device__ __forceinline__ void mma16816(float* c, const uint32_t* a, const uint32_t* b) {
    asm volatile("mma.sync.aligned.m16n8k16.row.col.f32.f16.f16.f32 "
        "{%0,%1,%2,%3}, {%4,%5,%6,%7}, {%8,%9}, {%0,%1,%2,%3};"
        : "+f"(c[0]), "+f"(c[1]), "+f"(c[2]), "+f"(c[3])
        : "r"(a[0]), "r"(a[1]), "r"(a[2]), "r"(a[3]), "r"(b[0]), "r"(b[1]));
}

__device__ __forceinline__ uint32_t sw128(uint32_t b) { return b ^ ((b >> 3) & 0x70); }
__device__ __forceinline__ bool lt2(float v, int i, float u, int j) {
    return v < u || (v == u && i < j);
}
__device__ __forceinline__ void merge2(float& v1, int& i1, float& v2, int& i2,
                                       float bv1, int bi1, float bv2, int bi2) {
    float n1, n2; int j1, j2;
    if (lt2(bv1, bi1, v1, i1)) {
        n1 = bv1; j1 = bi1;
        if (lt2(v1, i1, bv2, bi2)) { n2 = v1; j2 = i1; } else { n2 = bv2; j2 = bi2; }
    } else {
        n1 = v1; j1 = i1;
        if (lt2(bv1, bi1, v2, i2)) { n2 = bv1; j2 = bi1; } else { n2 = v2; j2 = i2; }
    }
    v1 = n1; i1 = j1; v2 = n2; i2 = j2;
}

// ================= small kernels =================
__global__ void k_zero() {
    int i = blockIdx.x * blockDim.x + threadIdx.x, st = gridDim.x * blockDim.x;
    for (int j = i; j < D * K; j += st) g_dw[j] = 0.f;
    for (int j = i; j < K; j += st) g_counts[j] = 0;
    if (i == 0) g_loss = 0.f;
}

__global__ void k_ce(const float* __restrict__ E) {
    int k = blockIdx.x * 256 + threadIdx.x;
    float s = 0.f;
    #pragma unroll 8
    for (int d = 0; d < D; d++) { float v = E[(size_t)d * K + k]; s = fmaf(v, v, s); }
    g_ce[k] = s;
}

// transpose E -> g_ET (fp32) and g_eh (fp16) in one pass
__global__ void k_transpose(const float* __restrict__ E) {
    __shared__ float t[32][33];
    int kb = blockIdx.x * 32, db = blockIdx.y * 32;
    int x = threadIdx.x, y0 = threadIdx.y;
    #pragma unroll
    for (int j = 0; j < 32; j += 8) t[y0 + j][x] = E[(size_t)(db + y0 + j) * K + kb + x];
    __syncthreads();
    #pragma unroll
    for (int j = 0; j < 32; j += 8) {
        float v = t[x][y0 + j];
        size_t o = (size_t)(kb + y0 + j) * D + db + x;
        g_ET[o] = v;
        g_eh[o] = __float2half_rn(v);
    }
}

__global__ void k_xh(const float* __restrict__ X) {
    size_t i = (size_t)blockIdx.x * 256 + threadIdx.x;
    float4 a = *(const float4*)(X + i * 8);
    float4 b = *(const float4*)(X + i * 8 + 4);
    __half h[8] = { __float2half_rn(a.x), __float2half_rn(a.y), __float2half_rn(a.z), __float2half_rn(a.w),
                    __float2half_rn(b.x), __float2half_rn(b.y), __float2half_rn(b.z), __float2half_rn(b.w) };
    *(uint4*)(g_xh + i * 8) = *(uint4*)h;
}

// ================= approx argmin GEMM (HMMA, K=256, 64x64 warp tiles) =================
// CTA = 128 rows x 128 codes, 4 warps (2x2 of 64x64). 3-stage cp.async pipeline.
// Epilogue: register top-2, shfl merge, 4KB smem cross-warp merge.
#define ST_SZ   32768
#define SM_CS   98304
#define SMEM_SZ 98816

__global__ void __launch_bounds__(128, 2)
k_argmin() {
    extern __shared__ char smem[];
    const int tid = threadIdx.x;
    const int wid = tid >> 5, lane = tid & 31;
    const int rt = blockIdx.x >> 5, cg = blockIdx.x & 31;
    const int row0 = rt * 128, kc0 = cg * 128;
    const int wr = wid >> 1, wc = wid & 1;       // 2x2 warp grid, 64x64 each
    const uint32_t sb = smem_to_u32(smem);

    float* cs = (float*)(smem + SM_CS);
    cs[tid] = g_ce[kc0 + tid];

    const __half* Ag = g_xh + (size_t)row0 * D;
    const __half* Bg = g_eh + (size_t)kc0 * D;

    float acc[4][8][4];
    #pragma unroll
    for (int mt = 0; mt < 4; mt++)
        #pragma unroll
        for (int nt = 0; nt < 8; nt++)
            #pragma unroll
            for (int j = 0; j < 4; j++) acc[mt][nt][j] = 0.f;

    auto issue = [&](int st) {
        int buf = st - (st / 3) * 3;
        uint32_t abase = sb + (uint32_t)buf * ST_SZ;
        uint32_t bbase = abase + 16384;
        int k0 = st * 64;
        #pragma unroll
        for (int j = 0; j < 8; j++) {
            int chunk = tid + j * 128;
            int r = chunk >> 3, cc = chunk & 7;
            uint32_t so = sw128((uint32_t)(r * 128 + cc * 16));
            cp16(abase + so, Ag + (size_t)r * D + k0 + cc * 8);
            cp16(bbase + so, Bg + (size_t)r * D + k0 + cc * 8);
        }
        CP_COMMIT();
    };

    issue(0); issue(1); issue(2);

    const int l15 = lane & 15;

    #pragma unroll 1
    for (int st = 0; st < 4; st++) {
        CP_WAIT2();
        __syncthreads();
        int buf = st - (st / 3) * 3;
        uint32_t abase = sb + (uint32_t)buf * ST_SZ;
        uint32_t bbase = abase + 16384;

        #pragma unroll
        for (int s = 0; s < 4; s++) {
            uint32_t af[4][4], bf[8][2];
            #pragma unroll
            for (int mt = 0; mt < 4; mt++) {
                uint32_t ro = sw128((uint32_t)((wr * 64 + mt * 16 + l15) * 128 + s * 32 + (lane >> 4) * 16));
                LDSM4(af[mt][0], af[mt][1], af[mt][2], af[mt][3], abase + ro);
            }
            // B: LDSM4 loads 2 adjacent n8 tiles (16 cols) x k16
            #pragma unroll
            for (int np = 0; np < 4; np++) {
                uint32_t ro = sw128((uint32_t)((wc * 64 + np * 16 + (lane & 7) + ((lane >> 4) & 1) * 8) * 128
                                               + s * 32 + ((lane >> 3) & 1) * 16));
                LDSM4(bf[2 * np][0], bf[2 * np][1], bf[2 * np + 1][0], bf[2 * np + 1][1], bbase + ro);
            }
            #pragma unroll
            for (int mt = 0; mt < 4; mt++)
                #pragma unroll
                for (int nt = 0; nt < 8; nt++)
                    mma16816(acc[mt][nt], af[mt], bf[nt]);
        }

        __syncthreads();
        if (st + 3 < 4) issue(st + 3);
        else CP_COMMIT();
    }

    // ---- epilogue: register top-2, ascending-col scan (first-min tie rule) ----
    float4* red = (float4*)smem;                  // [wc][row]: 2*128 float4 = 4KB
    #pragma unroll
    for (int mt = 0; mt < 4; mt++)
        #pragma unroll
        for (int h = 0; h < 2; h++) {
            float v1 = 3.4e38f, v2 = 3.4e38f; int i1 = 0x7fffffff, i2 = 0x7fffffff;
            #pragma unroll
            for (int nt = 0; nt < 8; nt++)
                #pragma unroll
                for (int c = 0; c < 2; c++) {
                    int col = wc * 64 + nt * 8 + (lane & 3) * 2 + c;
                    float v = cs[col] - 2.0f * acc[mt][nt][h * 2 + c];
                    if (v < v1) { v2 = v1; i2 = i1; v1 = v; i1 = col; }
                    else if (v < v2) { v2 = v; i2 = col; }
                }
            #pragma unroll
            for (int o = 1; o <= 2; o <<= 1) {
                float pv1 = __shfl_xor_sync(0xffffffffu, v1, o);
                int   pi1 = __shfl_xor_sync(0xffffffffu, i1, o);
                float pv2 = __shfl_xor_sync(0xffffffffu, v2, o);
                int   pi2 = __shfl_xor_sync(0xffffffffu, i2, o);
                merge2(v1, i1, v2, i2, pv1, pi1, pv2, pi2);
            }
            if ((lane & 3) == 0) {
                int row = wr * 64 + mt * 16 + (lane >> 2) + 8 * h;
                red[wc * 128 + row] = make_float4(v1, __int_as_float(i1), v2, __int_as_float(i2));
            }
        }
    __syncthreads();

    {
        float4 a = red[tid];                      // cols 0-63 half
        float4 b = red[128 + tid];                // cols 64-127 half
        float v1 = a.x, v2 = a.z; int i1 = __float_as_int(a.y), i2 = __float_as_int(a.w);
        merge2(v1, i1, v2, i2, b.x, __float_as_int(b.y), b.z, __float_as_int(b.w));
        g_t2[(size_t)(row0 + tid) * 32 + cg] =
            make_float4(v1, __int_as_float(kc0 + i1), v2, __int_as_float(kc0 + i2));
    }
}

// ================= select (top-4 merge + exact rescore) + scatter =================
__global__ void __launch_bounds__(256)
k_select(const float* __restrict__ X, float* __restrict__ out_q, float* __restrict__ out_idx) {
    const int wid = threadIdx.x >> 5, lane = threadIdx.x & 31;
    const size_t n = (size_t)blockIdx.x * 8 + wid;

    float4 cc = g_t2[n * 32 + lane];
    float t4v[4]; int t4i[4];
    t4v[0] = cc.x; t4i[0] = __float_as_int(cc.y);
    t4v[1] = cc.z; t4i[1] = __float_as_int(cc.w);
    t4v[2] = t4v[3] = 3.4e38f; t4i[2] = t4i[3] = 0x7fffffff;

    #pragma unroll
    for (int o = 1; o < 32; o <<= 1) {
        float rv[4]; int ri[4];
        #pragma unroll
        for (int s = 0; s < 4; s++) {
            rv[s] = __shfl_xor_sync(0xffffffffu, t4v[s], o);
            ri[s] = __shfl_xor_sync(0xffffffffu, t4i[s], o);
        }
        #pragma unroll
        for (int s = 0; s < 4; s++) {
            float v = rv[s]; int i = ri[s];
            if (lt2(v, i, t4v[3], t4i[3])) {
                if (lt2(v, i, t4v[0], t4i[0])) {
                    t4v[3]=t4v[2]; t4i[3]=t4i[2]; t4v[2]=t4v[1]; t4i[2]=t4i[1];
                    t4v[1]=t4v[0]; t4i[1]=t4i[0]; t4v[0]=v; t4i[0]=i;
                } else if (lt2(v, i, t4v[1], t4i[1])) {
                    t4v[3]=t4v[2]; t4i[3]=t4i[2]; t4v[2]=t4v[1]; t4i[2]=t4i[1];
                    t4v[1]=v; t4i[1]=i;
                } else if (lt2(v, i, t4v[2], t4i[2])) {
                    t4v[3]=t4v[2]; t4i[3]=t4i[2]; t4v[2]=v; t4i[2]=i;
                } else {
                    t4v[3]=v; t4i[3]=i;
                }
            }
        }
    }

    // exact fp32 rescore of 4 candidates: hoisted gathers (MLP), ce reused for ||e||^2
    const float4* xr = (const float4*)(X + n * D);
    float4 xa = xr[lane * 2], xb = xr[lane * 2 + 1];
    float4 ea[4], eb[4];
    float cq[4];
    #pragma unroll
    for (int c = 0; c < 4; c++) {
        const float4* er = (const float4*)(g_ET + (size_t)t4i[c] * D);
        ea[c] = er[lane * 2];
        eb[c] = er[lane * 2 + 1];
        cq[c] = g_ce[t4i[c]];
    }
    float bs = 3.4e38f; int bk = 0x7fffffff;
    #pragma unroll
    for (int c = 0; c < 4; c++) {
        float d = xa.x*ea[c].x + xa.y*ea[c].y + xa.z*ea[c].z + xa.w*ea[c].w
                + xb.x*eb[c].x + xb.y*eb[c].y + xb.z*eb[c].z + xb.w*eb[c].w;
        #pragma unroll
        for (int o = 16; o; o >>= 1) d += __shfl_xor_sync(0xffffffffu, d, o);
        float s = cq[c] - 2.0f * d;
        int k = t4i[c];
        if (s < bs || (s == bs && k < bk)) { bs = s; bk = k; }
    }

    // scatter: quantized, loss, dw atomics [d][k], counts
    const float4* er = (const float4*)(g_ET + (size_t)bk * D);
    float4 qa = er[lane * 2], qb = er[lane * 2 + 1];
    float4* qo = (float4*)(out_q + n * D);
    qo[lane * 2] = qa; qo[lane * 2 + 1] = qb;
    float dx0 = qa.x - xa.x, dx1 = qa.y - xa.y, dx2 = qa.z - xa.z, dx3 = qa.w - xa.w;
    float dx4 = qb.x - xb.x, dx5 = qb.y - xb.y, dx6 = qb.z - xb.z, dx7 = qb.w - xb.w;
    float ls = dx0*dx0 + dx1*dx1 + dx2*dx2 + dx3*dx3 + dx4*dx4 + dx5*dx5 + dx6*dx6 + dx7*dx7;

    int d0 = lane * 8;
    atomicAdd(&g_dw[(size_t)(d0 + 0) * K + bk], xa.x);
    atomicAdd(&g_dw[(size_t)(d0 + 1) * K + bk], xa.y);
    atomicAdd(&g_dw[(size_t)(d0 + 2) * K + bk], xa.z);
    atomicAdd(&g_dw[(size_t)(d0 + 3) * K + bk], xa.w);
    atomicAdd(&g_dw[(size_t)(d0 + 4) * K + bk], xb.x);
    atomicAdd(&g_dw[(size_t)(d0 + 5) * K + bk], xb.y);
    atomicAdd(&g_dw[(size_t)(d0 + 6) * K + bk], xb.z);
    atomicAdd(&g_dw[(size_t)(d0 + 7) * K + bk], xb.w);

    #pragma unroll
    for (int o = 16; o; o >>= 1) ls += __shfl_down_sync(0xffffffffu, ls, o);
    if (lane == 0) {
        atomicAdd(&g_loss, ls);
        atomicAdd(&g_counts[bk], 1);
        out_idx[n] = (float)bk;
    }
}

// ================= stats / new embeddings =================
__global__ void k_stats(const float* __restrict__ ema_counter,
                        const float* __restrict__ ema_cluster,
                        float* __restrict__ out) {
    __shared__ float sh[64];
    __shared__ float sh_n;
    int tid = threadIdx.x;
    float counter = ema_counter[0] + 1.0f;
    float bias = 1.0f - powf(DECAY, counter);
    float cavg[4]; float npart = 0.f, epart = 0.f;
    #pragma unroll
    for (int j = 0; j < 4; j++) {
        int k = tid + j * 1024;
        float cnt = (float)g_counts[k];
        float ch = ema_cluster[k] * DECAY + cnt * ONE_MINUS_DECAY;
        float ca = ch / bias;
        cavg[j] = ca; npart += ca;
        float p = cnt * (1.0f / (float)NROWS);
        epart += p * logf(p + 1e-10f);
    }
    #pragma unroll
    for (int o = 16; o; o >>= 1) {
        npart += __shfl_down_sync(0xffffffffu, npart, o);
        epart += __shfl_down_sync(0xffffffffu, epart, o);
    }
    if ((tid & 31) == 0) { sh[tid >> 5] = npart; sh[32 + (tid >> 5)] = epart; }
    __syncthreads();
    if (tid < 32) {
        float a = sh[tid], b = sh[32 + tid];
        #pragma unroll
        for (int o = 16; o; o >>= 1) {
            a += __shfl_down_sync(0xffffffffu, a, o);
            b += __shfl_down_sync(0xffffffffu, b, o);
        }
        if (tid == 0) {
            sh_n = a;
            out[OFF_PERP] = expf(-b);
            float el = g_loss / (float)((size_t)NROWS * D);
            out[OFF_LOSS] = el + COMMIT * el;
            g_bias = bias;
        }
    }
    __syncthreads();
    float n = sh_n;
    #pragma unroll
    for (int j = 0; j < 4; j++) {
        int k = tid + j * 1024;
        g_cnorm[k] = (cavg[j] + EPSV) / (n + (float)K * EPSV) * n;
    }
}

__global__ void k_newemb(const float* __restrict__ ema_dw, float* __restrict__ out_ne) {
    int i = blockIdx.x * 256 + threadIdx.x;
    int k = i & (K - 1);
    float dwh = ema_dw[i] * DECAY + g_dw[i] * ONE_MINUS_DECAY;
    out_ne[i] = (dwh / g_bias) / g_cnorm[k];
}

// ================= launch =================
// k_argmin stays 4th so the ncu window keeps profiling it.
extern "C" void kernel_launch(void* const* d_in, const int* in_sizes, int n_in,
                              void* d_out, int out_size) {
    const float* x   = (const float*)d_in[0];
    const float* emb = (const float*)d_in[1];
    const float* ctr = (const float*)d_in[2];
    const float* ecl = (const float*)d_in[3];
    const float* edw = (const float*)d_in[4];
    float* out = (float*)d_out;

    cudaFuncSetAttribute(k_argmin, cudaFuncAttributeMaxDynamicSharedMemorySize, SMEM_SZ);

    k_ce<<<K / 256, 256>>>(emb);
    k_transpose<<<dim3(K / 32, D / 32), dim3(32, 8)>>>(emb);
    k_xh<<<((size_t)NROWS * D / 8) / 256, 256>>>(x);
    k_argmin<<<8192, 128, SMEM_SZ>>>();
    k_zero<<<1024, 256>>>();
    k_select<<<NROWS / 8, 256>>>(x, out + OFF_Q, out + OFF_IDX);
    k_stats<<<1, 1024>>>(ctr, ecl, out);
    k_newemb<<<(D * K) / 256, 256>>>(edw, out + OFF_NE);
}

// round 12
// speedup vs baseline: 1.1132x; 1.1132x over previous
#include <cuda_runtime.h>
#include <cuda_fp16.h>
#include <cstdint>

#define NROWS 32768
#define D 256
#define K 4096
#define DECAY 0.99f
#define ONE_MINUS_DECAY 0.01f
#define EPSV 1e-5f
#define COMMIT 0.25f

static const size_t OFF_Q    = 0;
static const size_t OFF_LOSS = 8388608;
static const size_t OFF_PERP = 8388609;
static const size_t OFF_IDX  = 8388610;
static const size_t OFF_NE   = 8421378;

// -------- device scratch --------
__device__ float g_ce[K];
__device__ float g_ET[(size_t)K * D];
__device__ __align__(16) __half g_xh[(size_t)NROWS * D];
__device__ __align__(16) __half g_eh[(size_t)K * D];
__device__ float g_dw[(size_t)D * K];             // [d][k]
__device__ int   g_counts[K];
__device__ float4 g_t2[(size_t)NROWS * 32];       // [row][cg] = {v1, i1, v2, i2}
__device__ float g_loss;
__device__ float g_bias;
__device__ float g_cnorm[K];

// ================= PTX helpers =================
__device__ __forceinline__ uint32_t smem_to_u32(const void* p) {
    uint32_t a;
    asm("{ .reg .u64 t; cvta.to.shared.u64 t, %1; cvt.u32.u64 %0, t; }" : "=r"(a) : "l"(p));
    return a;
}
__device__ __forceinline__ void cp16(uint32_t saddr, const void* g) {
    asm volatile("cp.async.cg.shared.global [%0], [%1], 16;" :: "r"(saddr), "l"(g));
}
#define CP_COMMIT() asm volatile("cp.async.commit_group;" ::: "memory")
#define CP_WAIT2()  asm volatile("cp.async.wait_group 2;" ::: "memory")

#define LDSM4(r0, r1, r2, r3, a) \
    asm volatile("ldmatrix.sync.aligned.m8n8.x4.shared.b16 {%0,%1,%2,%3}, [%4];" \
        : "=r"(r0), "=r"(r1), "=r"(r2), "=r"(r3) : "r"(a))

__device__ __forceinline__ void mma16816(float* c, const uint32_t* a, const uint32_t* b) {
    asm volatile("mma.sync.aligned.m16n8k16.row.col.f32.f16.f16.f32 "
        "{%0,%1,%2,%3}, {%4,%5,%6,%7}, {%8,%9}, {%0,%1,%2,%3};"
        : "+f"(c[0]), "+f"(c[1]), "+f"(c[2]), "+f"(c[3])
        : "r"(a[0]), "r"(a[1]), "r"(a[2]), "r"(a[3]), "r"(b[0]), "r"(b[1]));
}

__device__ __forceinline__ uint32_t sw128(uint32_t b) { return b ^ ((b >> 3) & 0x70); }
__device__ __forceinline__ bool lt2(float v, int i, float u, int j) {
    return v < u || (v == u && i < j);
}
__device__ __forceinline__ void merge2(float& v1, int& i1, float& v2, int& i2,
                                       float bv1, int bi1, float bv2, int bi2) {
    float n1, n2; int j1, j2;
    if (lt2(bv1, bi1, v1, i1)) {
        n1 = bv1; j1 = bi1;
        if (lt2(v1, i1, bv2, bi2)) { n2 = v1; j2 = i1; } else { n2 = bv2; j2 = bi2; }
    } else {
        n1 = v1; j1 = i1;
        if (lt2(bv1, bi1, v2, i2)) { n2 = bv1; j2 = bi1; } else { n2 = v2; j2 = i2; }
    }
    v1 = n1; i1 = j1; v2 = n2; i2 = j2;
}

// ================= small kernels =================
__global__ void k_zero() {
    int i = blockIdx.x * blockDim.x + threadIdx.x, st = gridDim.x * blockDim.x;
    for (int j = i; j < D * K; j += st) g_dw[j] = 0.f;
    for (int j = i; j < K; j += st) g_counts[j] = 0;
    if (i == 0) g_loss = 0.f;
}

__global__ void k_ce(const float* __restrict__ E) {
    int k = blockIdx.x * 256 + threadIdx.x;
    float s = 0.f;
    #pragma unroll 8
    for (int d = 0; d < D; d++) { float v = E[(size_t)d * K + k]; s = fmaf(v, v, s); }
    g_ce[k] = s;
}

// transpose E -> g_ET (fp32) and g_eh (fp16) in one pass
__global__ void k_transpose(const float* __restrict__ E) {
    __shared__ float t[32][33];
    int kb = blockIdx.x * 32, db = blockIdx.y * 32;
    int x = threadIdx.x, y0 = threadIdx.y;
    #pragma unroll
    for (int j = 0; j < 32; j += 8) t[y0 + j][x] = E[(size_t)(db + y0 + j) * K + kb + x];
    __syncthreads();
    #pragma unroll
    for (int j = 0; j < 32; j += 8) {
        float v = t[x][y0 + j];
        size_t o = (size_t)(kb + y0 + j) * D + db + x;
        g_ET[o] = v;
        g_eh[o] = __float2half_rn(v);
    }
}

__global__ void k_xh(const float* __restrict__ X) {
    size_t i = (size_t)blockIdx.x * 256 + threadIdx.x;
    float4 a = *(const float4*)(X + i * 8);
    float4 b = *(const float4*)(X + i * 8 + 4);
    __half h[8] = { __float2half_rn(a.x), __float2half_rn(a.y), __float2half_rn(a.z), __float2half_rn(a.w),
                    __float2half_rn(b.x), __float2half_rn(b.y), __float2half_rn(b.z), __float2half_rn(b.w) };
    *(uint4*)(g_xh + i * 8) = *(uint4*)h;
}

// ================= approx argmin GEMM (HMMA, K=256, top-2 per 128-tile) =================
// CTA = 128 rows x 128 codes, 8 warps (2x4 of 64x32). 3-stage cp.async pipeline.
// Epilogue: register top-2, quad shfl merge, 8KB smem cross-warp merge.
#define ST_SZ   32768
#define SM_CS   98304
#define SMEM_SZ 98816

__global__ void __launch_bounds__(256, 2)
k_argmin() {
    extern __shared__ char smem[];
    const int tid = threadIdx.x;
    const int wid = tid >> 5, lane = tid & 31;
    const int rt = blockIdx.x >> 5, cg = blockIdx.x & 31;
    const int row0 = rt * 128, kc0 = cg * 128;
    const int wr = wid >> 2, wc = wid & 3;
    const uint32_t sb = smem_to_u32(smem);

    float* cs = (float*)(smem + SM_CS);
    if (tid < 128) cs[tid] = g_ce[kc0 + tid];

    const __half* Ag = g_xh + (size_t)row0 * D;
    const __half* Bg = g_eh + (size_t)kc0 * D;

    float acc[4][4][4];
    #pragma unroll
    for (int mt = 0; mt < 4; mt++)
        #pragma unroll
        for (int nt = 0; nt < 4; nt++)
            #pragma unroll
            for (int j = 0; j < 4; j++) acc[mt][nt][j] = 0.f;

    auto issue = [&](int st) {
        int buf = st - (st / 3) * 3;
        uint32_t abase = sb + (uint32_t)buf * ST_SZ;
        uint32_t bbase = abase + 16384;
        int k0 = st * 64;
        #pragma unroll
        for (int j = 0; j < 4; j++) {
            int chunk = tid + j * 256;
            int r = chunk >> 3, cc = chunk & 7;
            uint32_t so = sw128((uint32_t)(r * 128 + cc * 16));
            cp16(abase + so, Ag + (size_t)r * D + k0 + cc * 8);
            cp16(bbase + so, Bg + (size_t)r * D + k0 + cc * 8);
        }
        CP_COMMIT();
    };

    issue(0); issue(1); issue(2);

    const int l15 = lane & 15;

    #pragma unroll 1
    for (int st = 0; st < 4; st++) {
        CP_WAIT2();
        __syncthreads();
        int buf = st - (st / 3) * 3;
        uint32_t abase = sb + (uint32_t)buf * ST_SZ;
        uint32_t bbase = abase + 16384;

        #pragma unroll
        for (int s = 0; s < 4; s++) {
            uint32_t af[4][4], bf[4][2];
            #pragma unroll
            for (int mt = 0; mt < 4; mt++) {
                uint32_t ro = sw128((uint32_t)((wr * 64 + mt * 16 + l15) * 128 + s * 32 + (lane >> 4) * 16));
                LDSM4(af[mt][0], af[mt][1], af[mt][2], af[mt][3], abase + ro);
            }
            // B: one LDSM4 covers two adjacent n8 tiles (16 cols) x k16
            #pragma unroll
            for (int np = 0; np < 2; np++) {
                uint32_t ro = sw128((uint32_t)((wc * 32 + np * 16 + (lane & 7) + ((lane >> 4) & 1) * 8) * 128
                                               + s * 32 + ((lane >> 3) & 1) * 16));
                LDSM4(bf[2 * np][0], bf[2 * np][1], bf[2 * np + 1][0], bf[2 * np + 1][1], bbase + ro);
            }
            #pragma unroll
            for (int mt = 0; mt < 4; mt++)
                #pragma unroll
                for (int nt = 0; nt < 4; nt++)
                    mma16816(acc[mt][nt], af[mt], bf[nt]);
        }

        __syncthreads();
        if (st + 3 < 4) issue(st + 3);
        else CP_COMMIT();
    }

    // ---- epilogue: register top-2 (ascending col), quad shfl merge, smem merge ----
    // hoist this thread's 8 ce values
    float cv[8];
    #pragma unroll
    for (int nt = 0; nt < 4; nt++) {
        int col = wc * 32 + nt * 8 + 2 * (lane & 3);
        cv[2 * nt]     = cs[col];
        cv[2 * nt + 1] = cs[col + 1];
    }
    __syncthreads();                              // cs read done; smem reuse below

    float4* red = (float4*)smem;                  // [wc][row]: 4*128 float4 = 8KB
    #pragma unroll
    for (int mt = 0; mt < 4; mt++)
        #pragma unroll
        for (int h = 0; h < 2; h++) {
            float v1 = 3.4e38f, v2 = 3.4e38f; int i1 = 0x7fffffff, i2 = 0x7fffffff;
            #pragma unroll
            for (int nt = 0; nt < 4; nt++)
                #pragma unroll
                for (int c = 0; c < 2; c++) {
                    int col = wc * 32 + nt * 8 + 2 * (lane & 3) + c;
                    float v = cv[2 * nt + c] - 2.0f * acc[mt][nt][h * 2 + c];
                    if (v < v1) { v2 = v1; i2 = i1; v1 = v; i1 = col; }
                    else if (v < v2) { v2 = v; i2 = col; }
                }
            #pragma unroll
            for (int o = 1; o <= 2; o <<= 1) {
                float pv1 = __shfl_xor_sync(0xffffffffu, v1, o);
                int   pi1 = __shfl_xor_sync(0xffffffffu, i1, o);
                float pv2 = __shfl_xor_sync(0xffffffffu, v2, o);
                int   pi2 = __shfl_xor_sync(0xffffffffu, i2, o);
                merge2(v1, i1, v2, i2, pv1, pi1, pv2, pi2);
            }
            if ((lane & 3) == 0) {
                int row = wr * 64 + mt * 16 + (lane >> 2) + 8 * h;
                red[wc * 128 + row] = make_float4(v1, __int_as_float(i1), v2, __int_as_float(i2));
            }
        }
    __syncthreads();

    if (tid < 128) {
        float4 a = red[tid];
        float v1 = a.x, v2 = a.z; int i1 = __float_as_int(a.y), i2 = __float_as_int(a.w);
        #pragma unroll
        for (int w = 1; w < 4; w++) {
            float4 b = red[w * 128 + tid];
            merge2(v1, i1, v2, i2, b.x, __float_as_int(b.y), b.z, __float_as_int(b.w));
        }
        g_t2[(size_t)(row0 + tid) * 32 + cg] =
            make_float4(v1, __int_as_float(kc0 + i1), v2, __int_as_float(kc0 + i2));
    }
}

// ================= select (top-4 merge + exact rescore) + scatter =================
__global__ void __launch_bounds__(256)
k_select(const float* __restrict__ X, float* __restrict__ out_q, float* __restrict__ out_idx) {
    const int wid = threadIdx.x >> 5, lane = threadIdx.x & 31;
    const size_t n = (size_t)blockIdx.x * 8 + wid;

    float4 cc = g_t2[n * 32 + lane];
    float t4v[4]; int t4i[4];
    t4v[0] = cc.x; t4i[0] = __float_as_int(cc.y);
    t4v[1] = cc.z; t4i[1] = __float_as_int(cc.w);
    t4v[2] = t4v[3] = 3.4e38f; t4i[2] = t4i[3] = 0x7fffffff;

    #pragma unroll
    for (int o = 1; o < 32; o <<= 1) {
        float rv[4]; int ri[4];
        #pragma unroll
        for (int s = 0; s < 4; s++) {
            rv[s] = __shfl_xor_sync(0xffffffffu, t4v[s], o);
            ri[s] = __shfl_xor_sync(0xffffffffu, t4i[s], o);
        }
        #pragma unroll
        for (int s = 0; s < 4; s++) {
            float v = rv[s]; int i = ri[s];
            if (lt2(v, i, t4v[3], t4i[3])) {
                if (lt2(v, i, t4v[0], t4i[0])) {
                    t4v[3]=t4v[2]; t4i[3]=t4i[2]; t4v[2]=t4v[1]; t4i[2]=t4i[1];
                    t4v[1]=t4v[0]; t4i[1]=t4i[0]; t4v[0]=v; t4i[0]=i;
                } else if (lt2(v, i, t4v[1], t4i[1])) {
                    t4v[3]=t4v[2]; t4i[3]=t4i[2]; t4v[2]=t4v[1]; t4i[2]=t4i[1];
                    t4v[1]=v; t4i[1]=i;
                } else if (lt2(v, i, t4v[2], t4i[2])) {
                    t4v[3]=t4v[2]; t4i[3]=t4i[2]; t4v[2]=v; t4i[2]=i;
                } else {
                    t4v[3]=v; t4i[3]=i;
                }
            }
        }
    }

    // exact fp32 rescore of 4 candidates: hoisted gathers (MLP), ce reused for ||e||^2
    const float4* xr = (const float4*)(X + n * D);
    float4 xa = xr[lane * 2], xb = xr[lane * 2 + 1];
    float4 ea[4], eb[4];
    float cq[4];
    #pragma unroll
    for (int c = 0; c < 4; c++) {
        const float4* er = (const float4*)(g_ET + (size_t)t4i[c] * D);
        ea[c] = er[lane * 2];
        eb[c] = er[lane * 2 + 1];
        cq[c] = g_ce[t4i[c]];
    }
    float bs = 3.4e38f; int bk = 0x7fffffff;
    #pragma unroll
    for (int c = 0; c < 4; c++) {
        float d = xa.x*ea[c].x + xa.y*ea[c].y + xa.z*ea[c].z + xa.w*ea[c].w
                + xb.x*eb[c].x + xb.y*eb[c].y + xb.z*eb[c].z + xb.w*eb[c].w;
        #pragma unroll
        for (int o = 16; o; o >>= 1) d += __shfl_xor_sync(0xffffffffu, d, o);
        float s = cq[c] - 2.0f * d;
        int k = t4i[c];
        if (s < bs || (s == bs && k < bk)) { bs = s; bk = k; }
    }

    // scatter: quantized, loss, dw atomics [d][k], counts
    const float4* er = (const float4*)(g_ET + (size_t)bk * D);
    float4 qa = er[lane * 2], qb = er[lane * 2 + 1];
    float4* qo = (float4*)(out_q + n * D);
    qo[lane * 2] = qa; qo[lane * 2 + 1] = qb;
    float dx0 = qa.x - xa.x, dx1 = qa.y - xa.y, dx2 = qa.z - xa.z, dx3 = qa.w - xa.w;
    float dx4 = qb.x - xb.x, dx5 = qb.y - xb.y, dx6 = qb.z - xb.z, dx7 = qb.w - xb.w;
    float ls = dx0*dx0 + dx1*dx1 + dx2*dx2 + dx3*dx3 + dx4*dx4 + dx5*dx5 + dx6*dx6 + dx7*dx7;

    int d0 = lane * 8;
    atomicAdd(&g_dw[(size_t)(d0 + 0) * K + bk], xa.x);
    atomicAdd(&g_dw[(size_t)(d0 + 1) * K + bk], xa.y);
    atomicAdd(&g_dw[(size_t)(d0 + 2) * K + bk], xa.z);
    atomicAdd(&g_dw[(size_t)(d0 + 3) * K + bk], xa.w);
    atomicAdd(&g_dw[(size_t)(d0 + 4) * K + bk], xb.x);
    atomicAdd(&g_dw[(size_t)(d0 + 5) * K + bk], xb.y);
    atomicAdd(&g_dw[(size_t)(d0 + 6) * K + bk], xb.z);
    atomicAdd(&g_dw[(size_t)(d0 + 7) * K + bk], xb.w);

    #pragma unroll
    for (int o = 16; o; o >>= 1) ls += __shfl_down_sync(0xffffffffu, ls, o);
    if (lane == 0) {
        atomicAdd(&g_loss, ls);
        atomicAdd(&g_counts[bk], 1);
        out_idx[n] = (float)bk;
    }
}

// ================= stats / new embeddings =================
__global__ void k_stats(const float* __restrict__ ema_counter,
                        const float* __restrict__ ema_cluster,
                        float* __restrict__ out) {
    __shared__ float sh[64];
    __shared__ float sh_n;
    int tid = threadIdx.x;
    float counter = ema_counter[0] + 1.0f;
    float bias = 1.0f - powf(DECAY, counter);
    float cavg[4]; float npart = 0.f, epart = 0.f;
    #pragma unroll
    for (int j = 0; j < 4; j++) {
        int k = tid + j * 1024;
        float cnt = (float)g_counts[k];
        float ch = ema_cluster[k] * DECAY + cnt * ONE_MINUS_DECAY;
        float ca = ch / bias;
        cavg[j] = ca; npart += ca;
        float p = cnt * (1.0f / (float)NROWS);
        epart += p * logf(p + 1e-10f);
    }
    #pragma unroll
    for (int o = 16; o; o >>= 1) {
        npart += __shfl_down_sync(0xffffffffu, npart, o);
        epart += __shfl_down_sync(0xffffffffu, epart, o);
    }
    if ((tid & 31) == 0) { sh[tid >> 5] = npart; sh[32 + (tid >> 5)] = epart; }
    __syncthreads();
    if (tid < 32) {
        float a = sh[tid], b = sh[32 + tid];
        #pragma unroll
        for (int o = 16; o; o >>= 1) {
            a += __shfl_down_sync(0xffffffffu, a, o);
            b += __shfl_down_sync(0xffffffffu, b, o);
        }
        if (tid == 0) {
            sh_n = a;
            out[OFF_PERP] = expf(-b);
            float el = g_loss / (float)((size_t)NROWS * D);
            out[OFF_LOSS] = el + COMMIT * el;
            g_bias = bias;
        }
    }
    __syncthreads();
    float n = sh_n;
    #pragma unroll
    for (int j = 0; j < 4; j++) {
        int k = tid + j * 1024;
        g_cnorm[k] = (cavg[j] + EPSV) / (n + (float)K * EPSV) * n;
    }
}

__global__ void k_newemb(const float* __restrict__ ema_dw, float* __restrict__ out_ne) {
    int i = blockIdx.x * 256 + threadIdx.x;
    int k = i & (K - 1);
    float dwh = ema_dw[i] * DECAY + g_dw[i] * ONE_MINUS_DECAY;
    out_ne[i] = (dwh / g_bias) / g_cnorm[k];
}

// ================= launch =================
// k_argmin stays 4th so the ncu window keeps profiling it.
extern "C" void kernel_launch(void* const* d_in, const int* in_sizes, int n_in,
                              void* d_out, int out_size) {
    const float* x   = (const float*)d_in[0];
    const float* emb = (const float*)d_in[1];
    const float* ctr = (const float*)d_in[2];
    const float* ecl = (const float*)d_in[3];
    const float* edw = (const float*)d_in[4];
    float* out = (float*)d_out;

    cudaFuncSetAttribute(k_argmin, cudaFuncAttributeMaxDynamicSharedMemorySize, SMEM_SZ);

    k_ce<<<K / 256, 256>>>(emb);
    k_transpose<<<dim3(K / 32, D / 32), dim3(32, 8)>>>(emb);
    k_xh<<<((size_t)NROWS * D / 8) / 256, 256>>>(x);
    k_argmin<<<8192, 256, SMEM_SZ>>>();
    k_zero<<<1024, 256>>>();
    k_select<<<NROWS / 8, 256>>>(x, out + OFF_Q, out + OFF_IDX);
    k_stats<<<1, 1024>>>(ctr, ecl, out);
    k_newemb<<<(D * K) / 256, 256>>>(edw, out + OFF_NE);
}

// round 13
// speedup vs baseline: 1.3544x; 1.2166x over previous
#include <cuda_runtime.h>
#include <cuda_fp16.h>
#include <cstdint>

#define NROWS 32768
#define D 256
#define K 4096
#define DECAY 0.99f
#define ONE_MINUS_DECAY 0.01f
#define EPSV 1e-5f
#define COMMIT 0.25f

static const size_t OFF_Q    = 0;
static const size_t OFF_LOSS = 8388608;
static const size_t OFF_PERP = 8388609;
static const size_t OFF_IDX  = 8388610;
static const size_t OFF_NE   = 8421378;

// -------- device scratch --------
__device__ float g_ce[K];
__device__ float g_ET[(size_t)K * D];
__device__ __align__(16) __half g_xh[(size_t)NROWS * D];
__device__ __align__(16) __half g_eh[(size_t)K * D];
__device__ float g_dw[(size_t)D * K];             // [d][k]
__device__ int   g_counts[K];
__device__ float4 g_t2[(size_t)NROWS * 32];       // [row][cg] = {v1, i1, v2, i2}
__device__ float g_loss;
__device__ float g_bias;
__device__ float g_cnorm[K];

// ================= PTX helpers =================
__device__ __forceinline__ uint32_t smem_to_u32(const void* p) {
    uint32_t a;
    asm("{ .reg .u64 t; cvta.to.shared.u64 t, %1; cvt.u32.u64 %0, t; }" : "=r"(a) : "l"(p));
    return a;
}
__device__ __forceinline__ void cp16(uint32_t saddr, const void* g) {
    asm volatile("cp.async.cg.shared.global [%0], [%1], 16;" :: "r"(saddr), "l"(g));
}
#define CP_COMMIT() asm volatile("cp.async.commit_group;" ::: "memory")
#define CP_WAIT2()  asm volatile("cp.async.wait_group 2;" ::: "memory")

#define LDSM4(r0, r1, r2, r3, a) \
    asm volatile("ldmatrix.sync.aligned.m8n8.x4.shared.b16 {%0,%1,%2,%3}, [%4];" \
        : "=r"(r0), "=r"(r1), "=r"(r2), "=r"(r3) : "r"(a))

__device__ __forceinline__ void mma16816(float* c, const uint32_t* a, const uint32_t* b) {
    asm volatile("mma.sync.aligned.m16n8k16.row.col.f32.f16.f16.f32 "
        "{%0,%1,%2,%3}, {%4,%5,%6,%7}, {%8,%9}, {%0,%1,%2,%3};"
        : "+f"(c[0]), "+f"(c[1]), "+f"(c[2]), "+f"(c[3])
        : "r"(a[0]), "r"(a[1]), "r"(a[2]), "r"(a[3]), "r"(b[0]), "r"(b[1]));
}

__device__ __forceinline__ uint32_t sw128(uint32_t b) { return b ^ ((b >> 3) & 0x70); }
__device__ __forceinline__ bool lt2(float v, int i, float u, int j) {
    return v < u || (v == u && i < j);
}
__device__ __forceinline__ void merge2(float& v1, int& i1, float& v2, int& i2,
                                       float bv1, int bi1, float bv2, int bi2) {
    float n1, n2; int j1, j2;
    if (lt2(bv1, bi1, v1, i1)) {
        n1 = bv1; j1 = bi1;
        if (lt2(v1, i1, bv2, bi2)) { n2 = v1; j2 = i1; } else { n2 = bv2; j2 = bi2; }
    } else {
        n1 = v1; j1 = i1;
        if (lt2(bv1, bi1, v2, i2)) { n2 = bv1; j2 = bi1; } else { n2 = v2; j2 = i2; }
    }
    v1 = n1; i1 = j1; v2 = n2; i2 = j2;
}

// ================= small kernels =================
__global__ void k_zero_ce() {
    g_ce[blockIdx.x * 256 + threadIdx.x] = 0.f;
}

__global__ void k_zero() {
    int i = blockIdx.x * blockDim.x + threadIdx.x, st = gridDim.x * blockDim.x;
    for (int j = i; j < D * K; j += st) g_dw[j] = 0.f;
    for (int j = i; j < K; j += st) g_counts[j] = 0;
    if (i == 0) g_loss = 0.f;
}

// transpose E -> g_ET (fp32) + g_eh (fp16) + partial ||e||^2 into g_ce, one pass
__global__ void k_transpose(const float* __restrict__ E) {
    __shared__ float t[32][33];
    int kb = blockIdx.x * 32, db = blockIdx.y * 32;
    int x = threadIdx.x, y0 = threadIdx.y;
    float p = 0.f;
    #pragma unroll
    for (int j = 0; j < 32; j += 8) {
        float v = E[(size_t)(db + y0 + j) * K + kb + x];
        t[y0 + j][x] = v;
        p = fmaf(v, v, p);
    }
    __syncthreads();
    #pragma unroll
    for (int j = 0; j < 32; j += 8) {
        float v = t[x][y0 + j];
        size_t o = (size_t)(kb + y0 + j) * D + db + x;
        g_ET[o] = v;
        g_eh[o] = __float2half_rn(v);
    }
    __syncthreads();
    t[y0][x] = p;
    __syncthreads();
    if (y0 == 0) {
        float s = ((t[0][x] + t[1][x]) + (t[2][x] + t[3][x]))
                + ((t[4][x] + t[5][x]) + (t[6][x] + t[7][x]));
        atomicAdd(&g_ce[kb + x], s);
    }
}

__global__ void k_xh(const float* __restrict__ X) {
    size_t i = (size_t)blockIdx.x * 256 + threadIdx.x;
    float4 a = *(const float4*)(X + i * 8);
    float4 b = *(const float4*)(X + i * 8 + 4);
    __half h[8] = { __float2half_rn(a.x), __float2half_rn(a.y), __float2half_rn(a.z), __float2half_rn(a.w),
                    __float2half_rn(b.x), __float2half_rn(b.y), __float2half_rn(b.z), __float2half_rn(b.w) };
    *(uint4*)(g_xh + i * 8) = *(uint4*)h;
}

// ================= approx argmin GEMM (HMMA, K=256, top-2 per 128-tile) =================
// CTA = 128 rows x 128 codes, 8 warps (2x4 of 64x32). 3-stage cp.async pipeline.
// Epilogue: register top-2 per quad-lane -> smem (16 entries/row) -> single final merge.
#define ST_SZ   32768
#define SM_CS   98304
#define SMEM_SZ 98816

__global__ void __launch_bounds__(256, 2)
k_argmin() {
    extern __shared__ char smem[];
    const int tid = threadIdx.x;
    const int wid = tid >> 5, lane = tid & 31;
    const int rt = blockIdx.x >> 5, cg = blockIdx.x & 31;
    const int row0 = rt * 128, kc0 = cg * 128;
    const int wr = wid >> 2, wc = wid & 3;
    const uint32_t sb = smem_to_u32(smem);

    float* cs = (float*)(smem + SM_CS);
    if (tid < 128) cs[tid] = g_ce[kc0 + tid];

    const __half* Ag = g_xh + (size_t)row0 * D;
    const __half* Bg = g_eh + (size_t)kc0 * D;

    float acc[4][4][4];
    #pragma unroll
    for (int mt = 0; mt < 4; mt++)
        #pragma unroll
        for (int nt = 0; nt < 4; nt++)
            #pragma unroll
            for (int j = 0; j < 4; j++) acc[mt][nt][j] = 0.f;

    auto issue = [&](int st) {
        int buf = st - (st / 3) * 3;
        uint32_t abase = sb + (uint32_t)buf * ST_SZ;
        uint32_t bbase = abase + 16384;
        int k0 = st * 64;
        #pragma unroll
        for (int j = 0; j < 4; j++) {
            int chunk = tid + j * 256;
            int r = chunk >> 3, cc = chunk & 7;
            uint32_t so = sw128((uint32_t)(r * 128 + cc * 16));
            cp16(abase + so, Ag + (size_t)r * D + k0 + cc * 8);
            cp16(bbase + so, Bg + (size_t)r * D + k0 + cc * 8);
        }
        CP_COMMIT();
    };

    issue(0); issue(1); issue(2);

    const int l15 = lane & 15;

    #pragma unroll 1
    for (int st = 0; st < 4; st++) {
        CP_WAIT2();
        __syncthreads();
        int buf = st - (st / 3) * 3;
        uint32_t abase = sb + (uint32_t)buf * ST_SZ;
        uint32_t bbase = abase + 16384;

        #pragma unroll
        for (int s = 0; s < 4; s++) {
            uint32_t af[4][4], bf[4][2];
            #pragma unroll
            for (int mt = 0; mt < 4; mt++) {
                uint32_t ro = sw128((uint32_t)((wr * 64 + mt * 16 + l15) * 128 + s * 32 + (lane >> 4) * 16));
                LDSM4(af[mt][0], af[mt][1], af[mt][2], af[mt][3], abase + ro);
            }
            // B: one LDSM4 covers two adjacent n8 tiles (16 cols) x k16
            #pragma unroll
            for (int np = 0; np < 2; np++) {
                uint32_t ro = sw128((uint32_t)((wc * 32 + np * 16 + (lane & 7) + ((lane >> 4) & 1) * 8) * 128
                                               + s * 32 + ((lane >> 3) & 1) * 16));
                LDSM4(bf[2 * np][0], bf[2 * np][1], bf[2 * np + 1][0], bf[2 * np + 1][1], bbase + ro);
            }
            #pragma unroll
            for (int mt = 0; mt < 4; mt++)
                #pragma unroll
                for (int nt = 0; nt < 4; nt++)
                    mma16816(acc[mt][nt], af[mt], bf[nt]);
        }

        __syncthreads();
        if (st + 3 < 4) issue(st + 3);
        else CP_COMMIT();
    }

    // ---- epilogue: per-quad-lane register top-2 -> smem, one final merge ----
    // hoist this thread's 8 ce values
    float cv[8];
    #pragma unroll
    for (int nt = 0; nt < 4; nt++) {
        int col = wc * 32 + nt * 8 + 2 * (lane & 3);
        cv[2 * nt]     = cs[col];
        cv[2 * nt + 1] = cs[col + 1];
    }

    // red layout: entry e = wc*4 + (lane&3), stride 129 rows of float4 (pad kills conflicts)
    float4* red = (float4*)smem;                  // 16 * 129 * 16B = 33KB (tile bufs done)
    #pragma unroll
    for (int mt = 0; mt < 4; mt++)
        #pragma unroll
        for (int h = 0; h < 2; h++) {
            float v1 = 3.4e38f, v2 = 3.4e38f; int i1 = 0x7fffffff, i2 = 0x7fffffff;
            #pragma unroll
            for (int nt = 0; nt < 4; nt++)
                #pragma unroll
                for (int c = 0; c < 2; c++) {
                    int col = wc * 32 + nt * 8 + 2 * (lane & 3) + c;
                    float v = cv[2 * nt + c] - 2.0f * acc[mt][nt][h * 2 + c];
                    if (v < v1) { v2 = v1; i2 = i1; v1 = v; i1 = col; }
                    else if (v < v2) { v2 = v; i2 = col; }
                }
            int row = wr * 64 + mt * 16 + (lane >> 2) + 8 * h;
            red[(size_t)(wc * 4 + (lane & 3)) * 129 + row] =
                make_float4(v1, __int_as_float(i1), v2, __int_as_float(i2));
        }
    __syncthreads();

    if (tid < 128) {
        float4 a = red[tid];
        float v1 = a.x, v2 = a.z; int i1 = __float_as_int(a.y), i2 = __float_as_int(a.w);
        #pragma unroll
        for (int e = 1; e < 16; e++) {
            float4 b = red[(size_t)e * 129 + tid];
            merge2(v1, i1, v2, i2, b.x, __float_as_int(b.y), b.z, __float_as_int(b.w));
        }
        g_t2[(size_t)(row0 + tid) * 32 + cg] =
            make_float4(v1, __int_as_float(kc0 + i1), v2, __int_as_float(kc0 + i2));
    }
}

// ================= select (top-4 merge + exact rescore) + scatter =================
__global__ void __launch_bounds__(256)
k_select(const float* __restrict__ X, float* __restrict__ out_q, float* __restrict__ out_idx) {
    const int wid = threadIdx.x >> 5, lane = threadIdx.x & 31;
    const size_t n = (size_t)blockIdx.x * 8 + wid;

    float4 cc = g_t2[n * 32 + lane];
    float t4v[4]; int t4i[4];
    t4v[0] = cc.x; t4i[0] = __float_as_int(cc.y);
    t4v[1] = cc.z; t4i[1] = __float_as_int(cc.w);
    t4v[2] = t4v[3] = 3.4e38f; t4i[2] = t4i[3] = 0x7fffffff;

    #pragma unroll
    for (int o = 1; o < 32; o <<= 1) {
        float rv[4]; int ri[4];
        #pragma unroll
        for (int s = 0; s < 4; s++) {
            rv[s] = __shfl_xor_sync(0xffffffffu, t4v[s], o);
            ri[s] = __shfl_xor_sync(0xffffffffu, t4i[s], o);
        }
        #pragma unroll
        for (int s = 0; s < 4; s++) {
            float v = rv[s]; int i = ri[s];
            if (lt2(v, i, t4v[3], t4i[3])) {
                if (lt2(v, i, t4v[0], t4i[0])) {
                    t4v[3]=t4v[2]; t4i[3]=t4i[2]; t4v[2]=t4v[1]; t4i[2]=t4i[1];
                    t4v[1]=t4v[0]; t4i[1]=t4i[0]; t4v[0]=v; t4i[0]=i;
                } else if (lt2(v, i, t4v[1], t4i[1])) {
                    t4v[3]=t4v[2]; t4i[3]=t4i[2]; t4v[2]=t4v[1]; t4i[2]=t4i[1];
                    t4v[1]=v; t4i[1]=i;
                } else if (lt2(v, i, t4v[2], t4i[2])) {
                    t4v[3]=t4v[2]; t4i[3]=t4i[2]; t4v[2]=v; t4i[2]=i;
                } else {
                    t4v[3]=v; t4i[3]=i;
                }
            }
        }
    }

    // exact fp32 rescore of 4 candidates: hoisted gathers (MLP), ce reused for ||e||^2
    const float4* xr = (const float4*)(X + n * D);
    float4 xa = xr[lane * 2], xb = xr[lane * 2 + 1];
    float4 ea[4], eb[4];
    float cq[4];
    #pragma unroll
    for (int c = 0; c < 4; c++) {
        const float4* er = (const float4*)(g_ET + (size_t)t4i[c] * D);
        ea[c] = er[lane * 2];
        eb[c] = er[lane * 2 + 1];
        cq[c] = g_ce[t4i[c]];
    }
    float bs = 3.4e38f; int bk = 0x7fffffff;
    #pragma unroll
    for (int c = 0; c < 4; c++) {
        float d = xa.x*ea[c].x + xa.y*ea[c].y + xa.z*ea[c].z + xa.w*ea[c].w
                + xb.x*eb[c].x + xb.y*eb[c].y + xb.z*eb[c].z + xb.w*eb[c].w;
        #pragma unroll
        for (int o = 16; o; o >>= 1) d += __shfl_xor_sync(0xffffffffu, d, o);
        float s = cq[c] - 2.0f * d;
        int k = t4i[c];
        if (s < bs || (s == bs && k < bk)) { bs = s; bk = k; }
    }

    // scatter: quantized, loss, dw atomics [d][k], counts
    const float4* er = (const float4*)(g_ET + (size_t)bk * D);
    float4 qa = er[lane * 2], qb = er[lane * 2 + 1];
    float4* qo = (float4*)(out_q + n * D);
    qo[lane * 2] = qa; qo[lane * 2 + 1] = qb;
    float dx0 = qa.x - xa.x, dx1 = qa.y - xa.y, dx2 = qa.z - xa.z, dx3 = qa.w - xa.w;
    float dx4 = qb.x - xb.x, dx5 = qb.y - xb.y, dx6 = qb.z - xb.z, dx7 = qb.w - xb.w;
    float ls = dx0*dx0 + dx1*dx1 + dx2*dx2 + dx3*dx3 + dx4*dx4 + dx5*dx5 + dx6*dx6 + dx7*dx7;

    int d0 = lane * 8;
    atomicAdd(&g_dw[(size_t)(d0 + 0) * K + bk], xa.x);
    atomicAdd(&g_dw[(size_t)(d0 + 1) * K + bk], xa.y);
    atomicAdd(&g_dw[(size_t)(d0 + 2) * K + bk], xa.z);
    atomicAdd(&g_dw[(size_t)(d0 + 3) * K + bk], xa.w);
    atomicAdd(&g_dw[(size_t)(d0 + 4) * K + bk], xb.x);
    atomicAdd(&g_dw[(size_t)(d0 + 5) * K + bk], xb.y);
    atomicAdd(&g_dw[(size_t)(d0 + 6) * K + bk], xb.z);
    atomicAdd(&g_dw[(size_t)(d0 + 7) * K + bk], xb.w);

    #pragma unroll
    for (int o = 16; o; o >>= 1) ls += __shfl_down_sync(0xffffffffu, ls, o);
    if (lane == 0) {
        atomicAdd(&g_loss, ls);
        atomicAdd(&g_counts[bk], 1);
        out_idx[n] = (float)bk;
    }
}

// ================= stats / new embeddings =================
__global__ void k_stats(const float* __restrict__ ema_counter,
                        const float* __restrict__ ema_cluster,
                        float* __restrict__ out) {
    __shared__ float sh[64];
    __shared__ float sh_n;
    int tid = threadIdx.x;
    float counter = ema_counter[0] + 1.0f;
    float bias = 1.0f - powf(DECAY, counter);
    float cavg[4]; float npart = 0.f, epart = 0.f;
    #pragma unroll
    for (int j = 0; j < 4; j++) {
        int k = tid + j * 1024;
        float cnt = (float)g_counts[k];
        float ch = ema_cluster[k] * DECAY + cnt * ONE_MINUS_DECAY;
        float ca = ch / bias;
        cavg[j] = ca; npart += ca;
        float p = cnt * (1.0f / (float)NROWS);
        epart += p * logf(p + 1e-10f);
    }
    #pragma unroll
    for (int o = 16; o; o >>= 1) {
        npart += __shfl_down_sync(0xffffffffu, npart, o);
        epart += __shfl_down_sync(0xffffffffu, epart, o);
    }
    if ((tid & 31) == 0) { sh[tid >> 5] = npart; sh[32 + (tid >> 5)] = epart; }
    __syncthreads();
    if (tid < 32) {
        float a = sh[tid], b = sh[32 + tid];
        #pragma unroll
        for (int o = 16; o; o >>= 1) {
            a += __shfl_down_sync(0xffffffffu, a, o);
            b += __shfl_down_sync(0xffffffffu, b, o);
        }
        if (tid == 0) {
            sh_n = a;
            out[OFF_PERP] = expf(-b);
            float el = g_loss / (float)((size_t)NROWS * D);
            out[OFF_LOSS] = el + COMMIT * el;
            g_bias = bias;
        }
    }
    __syncthreads();
    float n = sh_n;
    #pragma unroll
    for (int j = 0; j < 4; j++) {
        int k = tid + j * 1024;
        g_cnorm[k] = (cavg[j] + EPSV) / (n + (float)K * EPSV) * n;
    }
}

__global__ void k_newemb(const float* __restrict__ ema_dw, float* __restrict__ out_ne) {
    int i = blockIdx.x * 256 + threadIdx.x;
    int k = i & (K - 1);
    float dwh = ema_dw[i] * DECAY + g_dw[i] * ONE_MINUS_DECAY;
    out_ne[i] = (dwh / g_bias) / g_cnorm[k];
}

// ================= launch =================
// k_argmin stays 4th so the ncu window keeps profiling it.
extern "C" void kernel_launch(void* const* d_in, const int* in_sizes, int n_in,
                              void* d_out, int out_size) {
    const float* x   = (const float*)d_in[0];
    const float* emb = (const float*)d_in[1];
    const float* ctr = (const float*)d_in[2];
    const float* ecl = (const float*)d_in[3];
    const float* edw = (const float*)d_in[4];
    float* out = (float*)d_out;

    cudaFuncSetAttribute(k_argmin, cudaFuncAttributeMaxDynamicSharedMemorySize, SMEM_SZ);

    k_zero_ce<<<K / 256, 256>>>();
    k_transpose<<<dim3(K / 32, D / 32), dim3(32, 8)>>>(emb);
    k_xh<<<((size_t)NROWS * D / 8) / 256, 256>>>(x);
    k_argmin<<<8192, 256, SMEM_SZ>>>();
    k_zero<<<1024, 256>>>();
    k_select<<<NROWS / 8, 256>>>(x, out + OFF_Q, out + OFF_IDX);
    k_stats<<<1, 1024>>>(ctr, ecl, out);
    k_newemb<<<(D * K) / 256, 256>>>(edw, out + OFF_NE);
}

// round 14
// speedup vs baseline: 1.3641x; 1.0072x over previous
#include <cuda_runtime.h>
#include <cuda_fp16.h>
#include <cstdint>

#define NROWS 32768
#define D 256
#define K 4096
#define DECAY 0.99f
#define ONE_MINUS_DECAY 0.01f
#define EPSV 1e-5f
#define COMMIT 0.25f

static const size_t OFF_Q    = 0;
static const size_t OFF_LOSS = 8388608;
static const size_t OFF_PERP = 8388609;
static const size_t OFF_IDX  = 8388610;
static const size_t OFF_NE   = 8421378;

// -------- device scratch --------
__device__ float g_ce[K];
__device__ float g_ET[(size_t)K * D];
__device__ __align__(16) __half g_xh[(size_t)NROWS * D];
__device__ __align__(16) __half g_eh[(size_t)K * D];
__device__ float g_dw[(size_t)D * K];             // [d][k]
__device__ int   g_counts[K];
__device__ float4 g_t2[(size_t)NROWS * 32];       // [row][cg] = {v1, i1, v2, i2}
__device__ float g_loss;
__device__ float g_bias;
__device__ float g_cnorm[K];

// ================= PTX helpers =================
__device__ __forceinline__ uint32_t smem_to_u32(const void* p) {
    uint32_t a;
    asm("{ .reg .u64 t; cvta.to.shared.u64 t, %1; cvt.u32.u64 %0, t; }" : "=r"(a) : "l"(p));
    return a;
}
__device__ __forceinline__ void cp16(uint32_t saddr, const void* g) {
    asm volatile("cp.async.cg.shared.global [%0], [%1], 16;" :: "r"(saddr), "l"(g));
}
#define CP_COMMIT() asm volatile("cp.async.commit_group;" ::: "memory")
#define CP_WAIT2()  asm volatile("cp.async.wait_group 2;" ::: "memory")

#define LDSM4(r0, r1, r2, r3, a) \
    asm volatile("ldmatrix.sync.aligned.m8n8.x4.shared.b16 {%0,%1,%2,%3}, [%4];" \
        : "=r"(r0), "=r"(r1), "=r"(r2), "=r"(r3) : "r"(a))

__device__ __forceinline__ void mma16816(float* c, const uint32_t* a, const uint32_t* b) {
    asm volatile("mma.sync.aligned.m16n8k16.row.col.f32.f16.f16.f32 "
        "{%0,%1,%2,%3}, {%4,%5,%6,%7}, {%8,%9}, {%0,%1,%2,%3};"
        : "+f"(c[0]), "+f"(c[1]), "+f"(c[2]), "+f"(c[3])
        : "r"(a[0]), "r"(a[1]), "r"(a[2]), "r"(a[3]), "r"(b[0]), "r"(b[1]));
}

__device__ __forceinline__ uint32_t sw128(uint32_t b) { return b ^ ((b >> 3) & 0x70); }
__device__ __forceinline__ bool lt2(float v, int i, float u, int j) {
    return v < u || (v == u && i < j);
}
__device__ __forceinline__ void merge2(float& v1, int& i1, float& v2, int& i2,
                                       float bv1, int bi1, float bv2, int bi2) {
    float n1, n2; int j1, j2;
    if (lt2(bv1, bi1, v1, i1)) {
        n1 = bv1; j1 = bi1;
        if (lt2(v1, i1, bv2, bi2)) { n2 = v1; j2 = i1; } else { n2 = bv2; j2 = bi2; }
    } else {
        n1 = v1; j1 = i1;
        if (lt2(bv1, bi1, v2, i2)) { n2 = bv1; j2 = bi1; } else { n2 = v2; j2 = i2; }
    }
    v1 = n1; i1 = j1; v2 = n2; i2 = j2;
}
__device__ __forceinline__ void ce64(uint64_t& a, uint64_t& b) {
    uint64_t lo = a < b ? a : b;
    uint64_t hi = a < b ? b : a;
    a = lo; b = hi;
}

// ================= small kernels =================
__global__ void k_zero_ce() {
    g_ce[blockIdx.x * 256 + threadIdx.x] = 0.f;
}

__global__ void k_zero() {
    int i = blockIdx.x * blockDim.x + threadIdx.x, st = gridDim.x * blockDim.x;
    for (int j = i; j < D * K; j += st) g_dw[j] = 0.f;
    for (int j = i; j < K; j += st) g_counts[j] = 0;
    if (i == 0) g_loss = 0.f;
}

// transpose E -> g_ET (fp32) + g_eh (fp16) + partial ||e||^2 into g_ce, one pass
__global__ void k_transpose(const float* __restrict__ E) {
    __shared__ float t[32][33];
    int kb = blockIdx.x * 32, db = blockIdx.y * 32;
    int x = threadIdx.x, y0 = threadIdx.y;
    float p = 0.f;
    #pragma unroll
    for (int j = 0; j < 32; j += 8) {
        float v = E[(size_t)(db + y0 + j) * K + kb + x];
        t[y0 + j][x] = v;
        p = fmaf(v, v, p);
    }
    __syncthreads();
    #pragma unroll
    for (int j = 0; j < 32; j += 8) {
        float v = t[x][y0 + j];
        size_t o = (size_t)(kb + y0 + j) * D + db + x;
        g_ET[o] = v;
        g_eh[o] = __float2half_rn(v);
    }
    __syncthreads();
    t[y0][x] = p;
    __syncthreads();
    if (y0 == 0) {
        float s = ((t[0][x] + t[1][x]) + (t[2][x] + t[3][x]))
                + ((t[4][x] + t[5][x]) + (t[6][x] + t[7][x]));
        atomicAdd(&g_ce[kb + x], s);
    }
}

__global__ void k_xh(const float* __restrict__ X) {
    size_t i = (size_t)blockIdx.x * 256 + threadIdx.x;
    float4 a = *(const float4*)(X + i * 8);
    float4 b = *(const float4*)(X + i * 8 + 4);
    __half h[8] = { __float2half_rn(a.x), __float2half_rn(a.y), __float2half_rn(a.z), __float2half_rn(a.w),
                    __float2half_rn(b.x), __float2half_rn(b.y), __float2half_rn(b.z), __float2half_rn(b.w) };
    *(uint4*)(g_xh + i * 8) = *(uint4*)h;
}

// ================= approx argmin GEMM (HMMA, K=256, top-2 per 128-tile) =================
// CTA = 128 rows x 128 codes, 8 warps (2x4 of 64x32). 3-stage cp.async pipeline.
// Epilogue: register top-2 per quad-lane -> smem (16 entries/row) -> single final merge.
#define ST_SZ   32768
#define SM_CS   98304
#define SMEM_SZ 98816

__global__ void __launch_bounds__(256, 2)
k_argmin() {
    extern __shared__ char smem[];
    const int tid = threadIdx.x;
    const int wid = tid >> 5, lane = tid & 31;
    const int rt = blockIdx.x >> 5, cg = blockIdx.x & 31;
    const int row0 = rt * 128, kc0 = cg * 128;
    const int wr = wid >> 2, wc = wid & 3;
    const uint32_t sb = smem_to_u32(smem);

    float* cs = (float*)(smem + SM_CS);
    if (tid < 128) cs[tid] = g_ce[kc0 + tid];

    const __half* Ag = g_xh + (size_t)row0 * D;
    const __half* Bg = g_eh + (size_t)kc0 * D;

    float acc[4][4][4];
    #pragma unroll
    for (int mt = 0; mt < 4; mt++)
        #pragma unroll
        for (int nt = 0; nt < 4; nt++)
            #pragma unroll
            for (int j = 0; j < 4; j++) acc[mt][nt][j] = 0.f;

    auto issue = [&](int st) {
        int buf = st - (st / 3) * 3;
        uint32_t abase = sb + (uint32_t)buf * ST_SZ;
        uint32_t bbase = abase + 16384;
        int k0 = st * 64;
        #pragma unroll
        for (int j = 0; j < 4; j++) {
            int chunk = tid + j * 256;
            int r = chunk >> 3, cc = chunk & 7;
            uint32_t so = sw128((uint32_t)(r * 128 + cc * 16));
            cp16(abase + so, Ag + (size_t)r * D + k0 + cc * 8);
            cp16(bbase + so, Bg + (size_t)r * D + k0 + cc * 8);
        }
        CP_COMMIT();
    };

    issue(0); issue(1); issue(2);

    const int l15 = lane & 15;

    #pragma unroll 1
    for (int st = 0; st < 4; st++) {
        CP_WAIT2();
        __syncthreads();
        int buf = st - (st / 3) * 3;
        uint32_t abase = sb + (uint32_t)buf * ST_SZ;
        uint32_t bbase = abase + 16384;

        #pragma unroll
        for (int s = 0; s < 4; s++) {
            uint32_t af[4][4], bf[4][2];
            #pragma unroll
            for (int mt = 0; mt < 4; mt++) {
                uint32_t ro = sw128((uint32_t)((wr * 64 + mt * 16 + l15) * 128 + s * 32 + (lane >> 4) * 16));
                LDSM4(af[mt][0], af[mt][1], af[mt][2], af[mt][3], abase + ro);
            }
            // B: one LDSM4 covers two adjacent n8 tiles (16 cols) x k16
            #pragma unroll
            for (int np = 0; np < 2; np++) {
                uint32_t ro = sw128((uint32_t)((wc * 32 + np * 16 + (lane & 7) + ((lane >> 4) & 1) * 8) * 128
                                               + s * 32 + ((lane >> 3) & 1) * 16));
                LDSM4(bf[2 * np][0], bf[2 * np][1], bf[2 * np + 1][0], bf[2 * np + 1][1], bbase + ro);
            }
            #pragma unroll
            for (int mt = 0; mt < 4; mt++)
                #pragma unroll
                for (int nt = 0; nt < 4; nt++)
                    mma16816(acc[mt][nt], af[mt], bf[nt]);
        }

        __syncthreads();
        if (st + 3 < 4) issue(st + 3);
        else CP_COMMIT();
    }

    // ---- epilogue: per-quad-lane register top-2 -> smem, one final merge ----
    // hoist this thread's 8 ce values
    float cv[8];
    #pragma unroll
    for (int nt = 0; nt < 4; nt++) {
        int col = wc * 32 + nt * 8 + 2 * (lane & 3);
        cv[2 * nt]     = cs[col];
        cv[2 * nt + 1] = cs[col + 1];
    }

    // red layout: entry e = wc*4 + (lane&3), stride 129 rows of float4 (pad kills conflicts)
    float4* red = (float4*)smem;                  // 16 * 129 * 16B = 33KB (tile bufs done)
    #pragma unroll
    for (int mt = 0; mt < 4; mt++)
        #pragma unroll
        for (int h = 0; h < 2; h++) {
            float v1 = 3.4e38f, v2 = 3.4e38f; int i1 = 0x7fffffff, i2 = 0x7fffffff;
            #pragma unroll
            for (int nt = 0; nt < 4; nt++)
                #pragma unroll
                for (int c = 0; c < 2; c++) {
                    int col = wc * 32 + nt * 8 + 2 * (lane & 3) + c;
                    float v = cv[2 * nt + c] - 2.0f * acc[mt][nt][h * 2 + c];
                    if (v < v1) { v2 = v1; i2 = i1; v1 = v; i1 = col; }
                    else if (v < v2) { v2 = v; i2 = col; }
                }
            int row = wr * 64 + mt * 16 + (lane >> 2) + 8 * h;
            red[(size_t)(wc * 4 + (lane & 3)) * 129 + row] =
                make_float4(v1, __int_as_float(i1), v2, __int_as_float(i2));
        }
    __syncthreads();

    if (tid < 128) {
        float4 a = red[tid];
        float v1 = a.x, v2 = a.z; int i1 = __float_as_int(a.y), i2 = __float_as_int(a.w);
        #pragma unroll
        for (int e = 1; e < 16; e++) {
            float4 b = red[(size_t)e * 129 + tid];
            merge2(v1, i1, v2, i2, b.x, __float_as_int(b.y), b.z, __float_as_int(b.w));
        }
        g_t2[(size_t)(row0 + tid) * 32 + cg] =
            make_float4(v1, __int_as_float(kc0 + i1), v2, __int_as_float(kc0 + i2));
    }
}

// ================= select (u64 bitonic top-4 + exact rescore) + scatter =================
__global__ void __launch_bounds__(256)
k_select(const float* __restrict__ X, float* __restrict__ out_q, float* __restrict__ out_idx) {
    const int wid = threadIdx.x >> 5, lane = threadIdx.x & 31;
    const size_t n = (size_t)blockIdx.x * 8 + wid;

    // pack candidates as (float_bits(v + 1024) << 32) | idx — u64 order == (v, idx) order
    float4 cc = g_t2[n * 32 + lane];
    uint64_t k0 = ((uint64_t)__float_as_uint(cc.x + 1024.0f) << 32) | (uint32_t)__float_as_int(cc.y);
    uint64_t k1 = ((uint64_t)__float_as_uint(cc.z + 1024.0f) << 32) | (uint32_t)__float_as_int(cc.w);
    uint64_t t0 = k0 < k1 ? k0 : k1;
    uint64_t t1 = k0 < k1 ? k1 : k0;
    uint64_t t2 = ~0ull, t3 = ~0ull;

    // butterfly: merge two sorted-4 lists, keep 4 smallest (min-extract + bitonic sort)
    #pragma unroll
    for (int o = 1; o < 32; o <<= 1) {
        uint64_t r0 = __shfl_xor_sync(0xffffffffu, t0, o);
        uint64_t r1 = __shfl_xor_sync(0xffffffffu, t1, o);
        uint64_t r2 = __shfl_xor_sync(0xffffffffu, t2, o);
        uint64_t r3 = __shfl_xor_sync(0xffffffffu, t3, o);
        t0 = t0 < r3 ? t0 : r3;
        t1 = t1 < r2 ? t1 : r2;
        t2 = t2 < r1 ? t2 : r1;
        t3 = t3 < r0 ? t3 : r0;
        ce64(t0, t2); ce64(t1, t3); ce64(t0, t1); ce64(t2, t3);
    }
    int t4i[4] = { (int)(uint32_t)t0, (int)(uint32_t)t1, (int)(uint32_t)t2, (int)(uint32_t)t3 };

    // exact fp32 rescore of 4 candidates: hoisted gathers (MLP), ce reused for ||e||^2
    const float4* xr = (const float4*)(X + n * D);
    float4 xa = xr[lane * 2], xb = xr[lane * 2 + 1];
    float4 ea[4], eb[4];
    float cq[4];
    #pragma unroll
    for (int c = 0; c < 4; c++) {
        const float4* er = (const float4*)(g_ET + (size_t)t4i[c] * D);
        ea[c] = er[lane * 2];
        eb[c] = er[lane * 2 + 1];
        cq[c] = g_ce[t4i[c]];
    }
    float bs = 3.4e38f; int bk = 0x7fffffff;
    #pragma unroll
    for (int c = 0; c < 4; c++) {
        float d = xa.x*ea[c].x + xa.y*ea[c].y + xa.z*ea[c].z + xa.w*ea[c].w
                + xb.x*eb[c].x + xb.y*eb[c].y + xb.z*eb[c].z + xb.w*eb[c].w;
        #pragma unroll
        for (int o = 16; o; o >>= 1) d += __shfl_xor_sync(0xffffffffu, d, o);
        float s = cq[c] - 2.0f * d;
        int k = t4i[c];
        if (s < bs || (s == bs && k < bk)) { bs = s; bk = k; }
    }

    // scatter: quantized, loss, dw atomics [d][k], counts
    const float4* er = (const float4*)(g_ET + (size_t)bk * D);
    float4 qa = er[lane * 2], qb = er[lane * 2 + 1];
    float4* qo = (float4*)(out_q + n * D);
    qo[lane * 2] = qa; qo[lane * 2 + 1] = qb;
    float dx0 = qa.x - xa.x, dx1 = qa.y - xa.y, dx2 = qa.z - xa.z, dx3 = qa.w - xa.w;
    float dx4 = qb.x - xb.x, dx5 = qb.y - xb.y, dx6 = qb.z - xb.z, dx7 = qb.w - xb.w;
    float ls = dx0*dx0 + dx1*dx1 + dx2*dx2 + dx3*dx3 + dx4*dx4 + dx5*dx5 + dx6*dx6 + dx7*dx7;

    int d0 = lane * 8;
    atomicAdd(&g_dw[(size_t)(d0 + 0) * K + bk], xa.x);
    atomicAdd(&g_dw[(size_t)(d0 + 1) * K + bk], xa.y);
    atomicAdd(&g_dw[(size_t)(d0 + 2) * K + bk], xa.z);
    atomicAdd(&g_dw[(size_t)(d0 + 3) * K + bk], xa.w);
    atomicAdd(&g_dw[(size_t)(d0 + 4) * K + bk], xb.x);
    atomicAdd(&g_dw[(size_t)(d0 + 5) * K + bk], xb.y);
    atomicAdd(&g_dw[(size_t)(d0 + 6) * K + bk], xb.z);
    atomicAdd(&g_dw[(size_t)(d0 + 7) * K + bk], xb.w);

    #pragma unroll
    for (int o = 16; o; o >>= 1) ls += __shfl_down_sync(0xffffffffu, ls, o);
    if (lane == 0) {
        atomicAdd(&g_loss, ls);
        atomicAdd(&g_counts[bk], 1);
        out_idx[n] = (float)bk;
    }
}

// ================= stats / new embeddings =================
__global__ void k_stats(const float* __restrict__ ema_counter,
                        const float* __restrict__ ema_cluster,
                        float* __restrict__ out) {
    __shared__ float sh[64];
    __shared__ float sh_n;
    int tid = threadIdx.x;
    float counter = ema_counter[0] + 1.0f;
    float bias = 1.0f - powf(DECAY, counter);
    float cavg[4]; float npart = 0.f, epart = 0.f;
    #pragma unroll
    for (int j = 0; j < 4; j++) {
        int k = tid + j * 1024;
        float cnt = (float)g_counts[k];
        float ch = ema_cluster[k] * DECAY + cnt * ONE_MINUS_DECAY;
        float ca = ch / bias;
        cavg[j] = ca; npart += ca;
        float p = cnt * (1.0f / (float)NROWS);
        epart += p * logf(p + 1e-10f);
    }
    #pragma unroll
    for (int o = 16; o; o >>= 1) {
        npart += __shfl_down_sync(0xffffffffu, npart, o);
        epart += __shfl_down_sync(0xffffffffu, epart, o);
    }
    if ((tid & 31) == 0) { sh[tid >> 5] = npart; sh[32 + (tid >> 5)] = epart; }
    __syncthreads();
    if (tid < 32) {
        float a = sh[tid], b = sh[32 + tid];
        #pragma unroll
        for (int o = 16; o; o >>= 1) {
            a += __shfl_down_sync(0xffffffffu, a, o);
            b += __shfl_down_sync(0xffffffffu, b, o);
        }
        if (tid == 0) {
            sh_n = a;
            out[OFF_PERP] = expf(-b);
            float el = g_loss / (float)((size_t)NROWS * D);
            out[OFF_LOSS] = el + COMMIT * el;
            g_bias = bias;
        }
    }
    __syncthreads();
    float n = sh_n;
    #pragma unroll
    for (int j = 0; j < 4; j++) {
        int k = tid + j * 1024;
        g_cnorm[k] = (cavg[j] + EPSV) / (n + (float)K * EPSV) * n;
    }
}

__global__ void k_newemb(const float* __restrict__ ema_dw, float* __restrict__ out_ne) {
    int i = blockIdx.x * 256 + threadIdx.x;
    int k = i & (K - 1);
    float dwh = ema_dw[i] * DECAY + g_dw[i] * ONE_MINUS_DECAY;
    out_ne[i] = (dwh / g_bias) / g_cnorm[k];
}

// ================= launch =================
// k_argmin stays 4th so the ncu window keeps profiling it.
extern "C" void kernel_launch(void* const* d_in, const int* in_sizes, int n_in,
                              void* d_out, int out_size) {
    const float* x   = (const float*)d_in[0];
    const float* emb = (const float*)d_in[1];
    const float* ctr = (const float*)d_in[2];
    const float* ecl = (const float*)d_in[3];
    const float* edw = (const float*)d_in[4];
    float* out = (float*)d_out;

    cudaFuncSetAttribute(k_argmin, cudaFuncAttributeMaxDynamicSharedMemorySize, SMEM_SZ);

    k_zero_ce<<<K / 256, 256>>>();
    k_transpose<<<dim3(K / 32, D / 32), dim3(32, 8)>>>(emb);
    k_xh<<<((size_t)NROWS * D / 8) / 256, 256>>>(x);
    k_argmin<<<8192, 256, SMEM_SZ>>>();
    k_zero<<<1024, 256>>>();
    k_select<<<NROWS / 8, 256>>>(x, out + OFF_Q, out + OFF_IDX);
    k_stats<<<1, 1024>>>(ctr, ecl, out);
    k_newemb<<<(D * K) / 256, 256>>>(edw, out + OFF_NE);
}

// round 16
// speedup vs baseline: 1.3819x; 1.0131x over previous
#include <cuda_runtime.h>
#include <cuda_fp16.h>
#include <cstdint>

#define NROWS 32768
#define D 256
#define K 4096
#define DECAY 0.99f
#define ONE_MINUS_DECAY 0.01f
#define EPSV 1e-5f
#define COMMIT 0.25f

static const size_t OFF_Q    = 0;
static const size_t OFF_LOSS = 8388608;
static const size_t OFF_PERP = 8388609;
static const size_t OFF_IDX  = 8388610;
static const size_t OFF_NE   = 8421378;

// -------- device scratch --------
__device__ float g_ce[K];
__device__ float g_ET[(size_t)K * D];
__device__ __align__(16) __half g_xh[(size_t)NROWS * D];
__device__ __align__(16) __half g_eh[(size_t)K * D];
__device__ float g_dw[(size_t)D * K];             // [d][k]
__device__ int   g_counts[K];
__device__ float4 g_t2[(size_t)NROWS * 32];       // [row][cg] = {v1, i1, v2, i2}
__device__ float g_loss;
__device__ float g_bias;
__device__ float g_cnorm[K];

// ================= PTX helpers =================
__device__ __forceinline__ uint32_t smem_to_u32(const void* p) {
    uint32_t a;
    asm("{ .reg .u64 t; cvta.to.shared.u64 t, %1; cvt.u32.u64 %0, t; }" : "=r"(a) : "l"(p));
    return a;
}
__device__ __forceinline__ void cp16(uint32_t saddr, const void* g) {
    asm volatile("cp.async.cg.shared.global [%0], [%1], 16;" :: "r"(saddr), "l"(g));
}
#define CP_COMMIT() asm volatile("cp.async.commit_group;" ::: "memory")
#define CP_WAIT2()  asm volatile("cp.async.wait_group 2;" ::: "memory")

#define LDSM4(r0, r1, r2, r3, a) \
    asm volatile("ldmatrix.sync.aligned.m8n8.x4.shared.b16 {%0,%1,%2,%3}, [%4];" \
        : "=r"(r0), "=r"(r1), "=r"(r2), "=r"(r3) : "r"(a))

__device__ __forceinline__ void mma16816(float* c, const uint32_t* a, const uint32_t* b) {
    asm volatile("mma.sync.aligned.m16n8k16.row.col.f32.f16.f16.f32 "
        "{%0,%1,%2,%3}, {%4,%5,%6,%7}, {%8,%9}, {%0,%1,%2,%3};"
        : "+f"(c[0]), "+f"(c[1]), "+f"(c[2]), "+f"(c[3])
        : "r"(a[0]), "r"(a[1]), "r"(a[2]), "r"(a[3]), "r"(b[0]), "r"(b[1]));
}

__device__ __forceinline__ uint32_t sw128(uint32_t b) { return b ^ ((b >> 3) & 0x70); }
__device__ __forceinline__ bool lt2(float v, int i, float u, int j) {
    return v < u || (v == u && i < j);
}
__device__ __forceinline__ void merge2(float& v1, int& i1, float& v2, int& i2,
                                       float bv1, int bi1, float bv2, int bi2) {
    float n1, n2; int j1, j2;
    if (lt2(bv1, bi1, v1, i1)) {
        n1 = bv1; j1 = bi1;
        if (lt2(v1, i1, bv2, bi2)) { n2 = v1; j2 = i1; } else { n2 = bv2; j2 = bi2; }
    } else {
        n1 = v1; j1 = i1;
        if (lt2(bv1, bi1, v2, i2)) { n2 = bv1; j2 = bi1; } else { n2 = v2; j2 = i2; }
    }
    v1 = n1; i1 = j1; v2 = n2; i2 = j2;
}
__device__ __forceinline__ void ce64(uint64_t& a, uint64_t& b) {
    uint64_t lo = a < b ? a : b;
    uint64_t hi = a < b ? b : a;
    a = lo; b = hi;
}

// ================= small kernels =================
__global__ void k_zero_ce() {
    g_ce[blockIdx.x * 256 + threadIdx.x] = 0.f;
}

// g_dw is D*K = 1,048,576 floats = 262,144 float4; grid 1024*256 covers it exactly, 1 per thread
__global__ void k_zero() {
    int i = blockIdx.x * blockDim.x + threadIdx.x;
    ((float4*)g_dw)[i] = make_float4(0.f, 0.f, 0.f, 0.f);
    if (i < K) g_counts[i] = 0;
    if (i == 0) g_loss = 0.f;
}

// transpose E -> g_ET (fp32) + g_eh (fp16) + partial ||e||^2 into g_ce, one pass
__global__ void k_transpose(const float* __restrict__ E) {
    __shared__ float t[32][33];
    int kb = blockIdx.x * 32, db = blockIdx.y * 32;
    int x = threadIdx.x, y0 = threadIdx.y;
    float p = 0.f;
    #pragma unroll
    for (int j = 0; j < 32; j += 8) {
        float v = E[(size_t)(db + y0 + j) * K + kb + x];
        t[y0 + j][x] = v;
        p = fmaf(v, v, p);
    }
    __syncthreads();
    #pragma unroll
    for (int j = 0; j < 32; j += 8) {
        float v = t[x][y0 + j];
        size_t o = (size_t)(kb + y0 + j) * D + db + x;
        g_ET[o] = v;
        g_eh[o] = __float2half_rn(v);
    }
    __syncthreads();
    t[y0][x] = p;
    __syncthreads();
    if (y0 == 0) {
        float s = ((t[0][x] + t[1][x]) + (t[2][x] + t[3][x]))
                + ((t[4][x] + t[5][x]) + (t[6][x] + t[7][x]));
        atomicAdd(&g_ce[kb + x], s);
    }
}

__global__ void k_xh(const float* __restrict__ X) {
    size_t i = (size_t)blockIdx.x * 256 + threadIdx.x;
    float4 a = *(const float4*)(X + i * 8);
    float4 b = *(const float4*)(X + i * 8 + 4);
    __half h[8] = { __float2half_rn(a.x), __float2half_rn(a.y), __float2half_rn(a.z), __float2half_rn(a.w),
                    __float2half_rn(b.x), __float2half_rn(b.y), __float2half_rn(b.z), __float2half_rn(b.w) };
    *(uint4*)(g_xh + i * 8) = *(uint4*)h;
}

// ================= approx argmin GEMM (HMMA, K=256, top-2 per 128-tile) =================
// CTA = 128 rows x 128 codes, 8 warps (2x4 of 64x32). 3-stage cp.async pipeline.
// Epilogue: register top-2 per quad-lane -> smem (16 entries/row) -> single final merge.
#define ST_SZ   32768
#define SM_CS   98304
#define SMEM_SZ 98816

__global__ void __launch_bounds__(256, 2)
k_argmin() {
    extern __shared__ char smem[];
    const int tid = threadIdx.x;
    const int wid = tid >> 5, lane = tid & 31;
    const int rt = blockIdx.x >> 5, cg = blockIdx.x & 31;
    const int row0 = rt * 128, kc0 = cg * 128;
    const int wr = wid >> 2, wc = wid & 3;
    const uint32_t sb = smem_to_u32(smem);

    float* cs = (float*)(smem + SM_CS);
    if (tid < 128) cs[tid] = g_ce[kc0 + tid];

    const __half* Ag = g_xh + (size_t)row0 * D;
    const __half* Bg = g_eh + (size_t)kc0 * D;

    float acc[4][4][4];
    #pragma unroll
    for (int mt = 0; mt < 4; mt++)
        #pragma unroll
        for (int nt = 0; nt < 4; nt++)
            #pragma unroll
            for (int j = 0; j < 4; j++) acc[mt][nt][j] = 0.f;

    auto issue = [&](int st) {
        int buf = st - (st / 3) * 3;
        uint32_t abase = sb + (uint32_t)buf * ST_SZ;
        uint32_t bbase = abase + 16384;
        int k0 = st * 64;
        #pragma unroll
        for (int j = 0; j < 4; j++) {
            int chunk = tid + j * 256;
            int r = chunk >> 3, cc = chunk & 7;
            uint32_t so = sw128((uint32_t)(r * 128 + cc * 16));
            cp16(abase + so, Ag + (size_t)r * D + k0 + cc * 8);
            cp16(bbase + so, Bg + (size_t)r * D + k0 + cc * 8);
        }
        CP_COMMIT();
    };

    issue(0); issue(1); issue(2);

    const int l15 = lane & 15;

    #pragma unroll 1
    for (int st = 0; st < 4; st++) {
        CP_WAIT2();
        __syncthreads();
        int buf = st - (st / 3) * 3;
        uint32_t abase = sb + (uint32_t)buf * ST_SZ;
        uint32_t bbase = abase + 16384;

        #pragma unroll
        for (int s = 0; s < 4; s++) {
            uint32_t af[4][4], bf[4][2];
            #pragma unroll
            for (int mt = 0; mt < 4; mt++) {
                uint32_t ro = sw128((uint32_t)((wr * 64 + mt * 16 + l15) * 128 + s * 32 + (lane >> 4) * 16));
                LDSM4(af[mt][0], af[mt][1], af[mt][2], af[mt][3], abase + ro);
            }
            // B: one LDSM4 covers two adjacent n8 tiles (16 cols) x k16
            #pragma unroll
            for (int np = 0; np < 2; np++) {
                uint32_t ro = sw128((uint32_t)((wc * 32 + np * 16 + (lane & 7) + ((lane >> 4) & 1) * 8) * 128
                                               + s * 32 + ((lane >> 3) & 1) * 16));
                LDSM4(bf[2 * np][0], bf[2 * np][1], bf[2 * np + 1][0], bf[2 * np + 1][1], bbase + ro);
            }
            #pragma unroll
            for (int mt = 0; mt < 4; mt++)
                #pragma unroll
                for (int nt = 0; nt < 4; nt++)
                    mma16816(acc[mt][nt], af[mt], bf[nt]);
        }

        __syncthreads();
        if (st + 3 < 4) issue(st + 3);
        else CP_COMMIT();
    }

    // ---- epilogue: per-quad-lane register top-2 -> smem, one final merge ----
    // hoist this thread's 8 ce values
    float cv[8];
    #pragma unroll
    for (int nt = 0; nt < 4; nt++) {
        int col = wc * 32 + nt * 8 + 2 * (lane & 3);
        cv[2 * nt]     = cs[col];
        cv[2 * nt + 1] = cs[col + 1];
    }

    // red layout: entry e = wc*4 + (lane&3), stride 129 rows of float4 (pad kills conflicts)
    float4* red = (float4*)smem;                  // 16 * 129 * 16B = 33KB (tile bufs done)
    #pragma unroll
    for (int mt = 0; mt < 4; mt++)
        #pragma unroll
        for (int h = 0; h < 2; h++) {
            float v1 = 3.4e38f, v2 = 3.4e38f; int i1 = 0x7fffffff, i2 = 0x7fffffff;
            #pragma unroll
            for (int nt = 0; nt < 4; nt++)
                #pragma unroll
                for (int c = 0; c < 2; c++) {
                    int col = wc * 32 + nt * 8 + 2 * (lane & 3) + c;
                    float v = cv[2 * nt + c] - 2.0f * acc[mt][nt][h * 2 + c];
                    if (v < v1) { v2 = v1; i2 = i1; v1 = v; i1 = col; }
                    else if (v < v2) { v2 = v; i2 = col; }
                }
            int row = wr * 64 + mt * 16 + (lane >> 2) + 8 * h;
            red[(size_t)(wc * 4 + (lane & 3)) * 129 + row] =
                make_float4(v1, __int_as_float(i1), v2, __int_as_float(i2));
        }
    __syncthreads();

    if (tid < 128) {
        float4 a = red[tid];
        float v1 = a.x, v2 = a.z; int i1 = __float_as_int(a.y), i2 = __float_as_int(a.w);
        #pragma unroll
        for (int e = 1; e < 16; e++) {
            float4 b = red[(size_t)e * 129 + tid];
            merge2(v1, i1, v2, i2, b.x, __float_as_int(b.y), b.z, __float_as_int(b.w));
        }
        g_t2[(size_t)(row0 + tid) * 32 + cg] =
            make_float4(v1, __int_as_float(kc0 + i1), v2, __int_as_float(kc0 + i2));
    }
}

// ================= select (u64 bitonic top-4 + gap-gated exact rescore) + scatter =================
// Gap theorem: every code except t0 has approx score >= v(t1) (unkept codes are >= their
// tile's kept-second >= global kept-2nd). fp16 dot error <= 2^-10*||x||*||e|| + pack quantum
// < 0.04, so score error < 0.08. If v(t1)-v(t0) > 0.125, t0 is provably the exact argmin.
#define GAP_MARGIN 0.125f

__global__ void __launch_bounds__(256)
k_select(const float* __restrict__ X, float* __restrict__ out_q, float* __restrict__ out_idx) {
    const int wid = threadIdx.x >> 5, lane = threadIdx.x & 31;
    const size_t n = (size_t)blockIdx.x * 8 + wid;

    // pack candidates as (float_bits(v + 1024) << 32) | idx — u64 order == (v, idx) order
    float4 cc = g_t2[n * 32 + lane];
    uint64_t k0 = ((uint64_t)__float_as_uint(cc.x + 1024.0f) << 32) | (uint32_t)__float_as_int(cc.y);
    uint64_t k1 = ((uint64_t)__float_as_uint(cc.z + 1024.0f) << 32) | (uint32_t)__float_as_int(cc.w);
    uint64_t t0 = k0 < k1 ? k0 : k1;
    uint64_t t1 = k0 < k1 ? k1 : k0;
    uint64_t t2 = ~0ull, t3 = ~0ull;

    // butterfly: merge two sorted-4 lists, keep 4 smallest (min-extract + bitonic sort)
    #pragma unroll
    for (int o = 1; o < 32; o <<= 1) {
        uint64_t r0 = __shfl_xor_sync(0xffffffffu, t0, o);
        uint64_t r1 = __shfl_xor_sync(0xffffffffu, t1, o);
        uint64_t r2 = __shfl_xor_sync(0xffffffffu, t2, o);
        uint64_t r3 = __shfl_xor_sync(0xffffffffu, t3, o);
        t0 = t0 < r3 ? t0 : r3;
        t1 = t1 < r2 ? t1 : r2;
        t2 = t2 < r1 ? t2 : r1;
        t3 = t3 < r0 ? t3 : r0;
        ce64(t0, t2); ce64(t1, t3); ce64(t0, t1); ce64(t2, t3);
    }

    const float4* xr = (const float4*)(X + n * D);
    float4 xa = xr[lane * 2], xb = xr[lane * 2 + 1];

    int bk;
    float av0 = __uint_as_float((uint32_t)(t0 >> 32)) - 1024.0f;
    float av1 = __uint_as_float((uint32_t)(t1 >> 32)) - 1024.0f;
    if (av1 - av0 > GAP_MARGIN) {
        // gap certifies approx winner is the exact argmin — skip rescore entirely
        bk = (int)(uint32_t)t0;
    } else {
        int t4i[4] = { (int)(uint32_t)t0, (int)(uint32_t)t1, (int)(uint32_t)t2, (int)(uint32_t)t3 };
        // exact fp32 rescore of 4 candidates: hoisted gathers (MLP), ce reused for ||e||^2
        float4 ea[4], eb[4];
        float cq[4];
        #pragma unroll
        for (int c = 0; c < 4; c++) {
            const float4* er = (const float4*)(g_ET + (size_t)t4i[c] * D);
            ea[c] = er[lane * 2];
            eb[c] = er[lane * 2 + 1];
            cq[c] = g_ce[t4i[c]];
        }
        float bs = 3.4e38f; bk = 0x7fffffff;
        #pragma unroll
        for (int c = 0; c < 4; c++) {
            float d = xa.x*ea[c].x + xa.y*ea[c].y + xa.z*ea[c].z + xa.w*ea[c].w
                    + xb.x*eb[c].x + xb.y*eb[c].y + xb.z*eb[c].z + xb.w*eb[c].w;
            #pragma unroll
            for (int o = 16; o; o >>= 1) d += __shfl_xor_sync(0xffffffffu, d, o);
            float s = cq[c] - 2.0f * d;
            int k = t4i[c];
            if (s < bs || (s == bs && k < bk)) { bs = s; bk = k; }
        }
    }

    // scatter: quantized, loss, dw atomics [d][k], counts
    const float4* er = (const float4*)(g_ET + (size_t)bk * D);
    float4 qa = er[lane * 2], qb = er[lane * 2 + 1];
    float4* qo = (float4*)(out_q + n * D);
    qo[lane * 2] = qa; qo[lane * 2 + 1] = qb;
    float dx0 = qa.x - xa.x, dx1 = qa.y - xa.y, dx2 = qa.z - xa.z, dx3 = qa.w - xa.w;
    float dx4 = qb.x - xb.x, dx5 = qb.y - xb.y, dx6 = qb.z - xb.z, dx7 = qb.w - xb.w;
    float ls = dx0*dx0 + dx1*dx1 + dx2*dx2 + dx3*dx3 + dx4*dx4 + dx5*dx5 + dx6*dx6 + dx7*dx7;

    int d0 = lane * 8;
    atomicAdd(&g_dw[(size_t)(d0 + 0) * K + bk], xa.x);
    atomicAdd(&g_dw[(size_t)(d0 + 1) * K + bk], xa.y);
    atomicAdd(&g_dw[(size_t)(d0 + 2) * K + bk], xa.z);
    atomicAdd(&g_dw[(size_t)(d0 + 3) * K + bk], xa.w);
    atomicAdd(&g_dw[(size_t)(d0 + 4) * K + bk], xb.x);
    atomicAdd(&g_dw[(size_t)(d0 + 5) * K + bk], xb.y);
    atomicAdd(&g_dw[(size_t)(d0 + 6) * K + bk], xb.z);
    atomicAdd(&g_dw[(size_t)(d0 + 7) * K + bk], xb.w);

    #pragma unroll
    for (int o = 16; o; o >>= 1) ls += __shfl_down_sync(0xffffffffu, ls, o);
    if (lane == 0) {
        atomicAdd(&g_loss, ls);
        atomicAdd(&g_counts[bk], 1);
        out_idx[n] = (float)bk;
    }
}

// ================= stats / new embeddings =================
__global__ void k_stats(const float* __restrict__ ema_counter,
                        const float* __restrict__ ema_cluster,
                        float* __restrict__ out) {
    __shared__ float sh[64];
    __shared__ float sh_n;
    int tid = threadIdx.x;
    float counter = ema_counter[0] + 1.0f;
    float bias = 1.0f - powf(DECAY, counter);
    float cavg[4]; float npart = 0.f, epart = 0.f;
    #pragma unroll
    for (int j = 0; j < 4; j++) {
        int k = tid + j * 1024;
        float cnt = (float)g_counts[k];
        float ch = ema_cluster[k] * DECAY + cnt * ONE_MINUS_DECAY;
        float ca = ch / bias;
        cavg[j] = ca; npart += ca;
        float p = cnt * (1.0f / (float)NROWS);
        epart += p * logf(p + 1e-10f);
    }
    #pragma unroll
    for (int o = 16; o; o >>= 1) {
        npart += __shfl_down_sync(0xffffffffu, npart, o);
        epart += __shfl_down_sync(0xffffffffu, epart, o);
    }
    if ((tid & 31) == 0) { sh[tid >> 5] = npart; sh[32 + (tid >> 5)] = epart; }
    __syncthreads();
    if (tid < 32) {
        float a = sh[tid], b = sh[32 + tid];
        #pragma unroll
        for (int o = 16; o; o >>= 1) {
            a += __shfl_down_sync(0xffffffffu, a, o);
            b += __shfl_down_sync(0xffffffffu, b, o);
        }
        if (tid == 0) {
            sh_n = a;
            out[OFF_PERP] = expf(-b);
            float el = g_loss / (float)((size_t)NROWS * D);
            out[OFF_LOSS] = el + COMMIT * el;
            g_bias = bias;
        }
    }
    __syncthreads();
    float n = sh_n;
    #pragma unroll
    for (int j = 0; j < 4; j++) {
        int k = tid + j * 1024;
        g_cnorm[k] = (cavg[j] + EPSV) / (n + (float)K * EPSV) * n;
    }
}

__global__ void k_newemb(const float* __restrict__ ema_dw, float* __restrict__ out_ne) {
    int i = blockIdx.x * 256 + threadIdx.x;
    int k = i & (K - 1);
    float dwh = ema_dw[i] * DECAY + g_dw[i] * ONE_MINUS_DECAY;
    out_ne[i] = (dwh / g_bias) / g_cnorm[k];
}

// ================= launch =================
// k_argmin stays 4th so the ncu window keeps profiling it.
extern "C" void kernel_launch(void* const* d_in, const int* in_sizes, int n_in,
                              void* d_out, int out_size) {
    const float* x   = (const float*)d_in[0];
    const float* emb = (const float*)d_in[1];
    const float* ctr = (const float*)d_in[2];
    const float* ecl = (const float*)d_in[3];
    const float* edw = (const float*)d_in[4];
    float* out = (float*)d_out;

    cudaFuncSetAttribute(k_argmin, cudaFuncAttributeMaxDynamicSharedMemorySize, SMEM_SZ);

    k_zero_ce<<<K / 256, 256>>>();
    k_transpose<<<dim3(K / 32, D / 32), dim3(32, 8)>>>(emb);
    k_xh<<<((size_t)NROWS * D / 8) / 256, 256>>>(x);
    k_argmin<<<8192, 256, SMEM_SZ>>>();
    k_zero<<<1024, 256>>>();
    k_select<<<NROWS / 8, 256>>>(x, out + OFF_Q, out + OFF_IDX);
    k_stats<<<1, 1024>>>(ctr, ecl, out);
    k_newemb<<<(D * K) / 256, 256>>>(edw, out + OFF_NE);
}